// round 2
// baseline (speedup 1.0000x reference)
#include <cuda_runtime.h>
#include <math.h>

#define B 8
#define C1 256
#define H1 88
#define W1 88
#define C2 256
#define H2 40
#define W2 40
#define NR 12800
#define NC 10

// ---- device scratch (no allocations allowed) ----
__device__ float g_h[B*C1*H1*W1];      // conv1 output (relu'd)   63.4 MB
__device__ float g_u[B*C2*H2*W2];      // prim conv out / squashed u
__device__ float g_uhat[B*NR*NC];      // u_hat[b][r][c]
__device__ float g_bij[NR*NC];         // routing logits
__device__ float g_v[B*NC];            // v[b][c]
__device__ float g_t1[B*512];
__device__ float g_t2[B*1024];

// ============================================================
// conv1: x(8,3,96,96) * w(256,3,9,9) stride1 VALID -> relu -> h(8,256,88,88)
// block: (88,2)=176 thr; each thread: 4 rows x 2 c_out = 8 accumulators
// ============================================================
__global__ void conv1_kernel(const float* __restrict__ x,
                             const float* __restrict__ w,
                             const float* __restrict__ bias){
    __shared__ float sW[486];          // 2 c_out x 3 ci x 81
    __shared__ float sIn[3*16*96];     // 3 ch x 16 rows x 96 cols
    int tx = threadIdx.x, ty = threadIdx.y;
    int tid = ty*88 + tx;
    int co0 = blockIdx.x*2;
    int y0  = blockIdx.y*8;
    int b   = blockIdx.z;

    for (int i = tid; i < 486; i += 176) sW[i] = w[co0*243 + i];
    for (int i = tid; i < 4608; i += 176){
        int ci = i / 1536, rem = i % 1536;
        int row = rem / 96, col = rem % 96;
        sIn[i] = x[((b*3+ci)*96 + (y0+row))*96 + col];
    }
    __syncthreads();

    float acc0[4], acc1[4];
    float b0 = bias[co0], b1 = bias[co0+1];
    #pragma unroll
    for (int r=0;r<4;r++){ acc0[r]=b0; acc1[r]=b1; }

    for (int ci=0; ci<3; ci++){
        for (int ky=0; ky<9; ky++){
            #pragma unroll
            for (int kx=0; kx<9; kx++){
                float w0 = sW[      ci*81 + ky*9 + kx];
                float w1 = sW[243 + ci*81 + ky*9 + kx];
                #pragma unroll
                for (int r=0;r<4;r++){
                    float iv = sIn[ci*1536 + (ty*4 + r + ky)*96 + tx + kx];
                    acc0[r] += w0*iv;
                    acc1[r] += w1*iv;
                }
            }
        }
    }
    #pragma unroll
    for (int r=0;r<4;r++){
        int y = y0 + ty*4 + r;
        g_h[((b*C1+co0  )*H1 + y)*W1 + tx] = fmaxf(acc0[r], 0.f);
        g_h[((b*C1+co0+1)*H1 + y)*W1 + tx] = fmaxf(acc1[r], 0.f);
    }
}

// ============================================================
// prim conv: h(8,256,88,88) * w(256,256,9,9) stride2 VALID -> u(8,256,40,40)
// block: 256 thr, tile = 64 c_out x (40 x 4) positions
// thread: 5 positions x 8 c_out = 40 accumulators; 13 LDS per 40 FMA
// ============================================================
__global__ void prim_kernel(const float* __restrict__ w,
                            const float* __restrict__ bias){
    __shared__ float sW[64*81];   // 20.7 KB
    __shared__ float sIn[15*88];  // 5.3 KB  (15 input rows, full 88 width)
    int tid   = threadIdx.x;
    int ytile = blockIdx.x;       // 0..9
    int cog   = blockIdx.y;       // 0..3
    int b     = blockIdx.z;       // 0..7
    int co0 = cog*64;
    int y0  = ytile*4;
    int pos_slot = tid >> 3;      // 0..31
    int co_slot  = tid & 7;       // 0..7

    int X[5], Y[5];
    #pragma unroll
    for (int j=0;j<5;j++){ int p = pos_slot + 32*j; X[j] = p % 40; Y[j] = p / 40; }

    float acc[5][8];
    #pragma unroll
    for (int c=0;c<8;c++){
        float bv = bias[co0 + co_slot + 8*c];
        #pragma unroll
        for (int j=0;j<5;j++) acc[j][c] = bv;
    }

    for (int ci=0; ci<256; ci++){
        __syncthreads();
        for (int i = tid; i < 64*81; i += 256){
            int c = i / 81, k = i % 81;
            sW[i] = w[((co0 + c)*256 + ci)*81 + k];
        }
        const float* hp = g_h + ((b*C1 + ci)*H1 + y0*2)*W1;  // 15 contiguous rows
        for (int i = tid; i < 15*88; i += 256) sIn[i] = hp[i];
        __syncthreads();

        for (int ky=0; ky<9; ky++){
            int ib[5];
            #pragma unroll
            for (int j=0;j<5;j++) ib[j] = (Y[j]*2 + ky)*88 + X[j]*2;
            #pragma unroll
            for (int kx=0; kx<9; kx++){
                float wv[8];
                #pragma unroll
                for (int c=0;c<8;c++) wv[c] = sW[(co_slot + 8*c)*81 + ky*9 + kx];
                #pragma unroll
                for (int j=0;j<5;j++){
                    float iv = sIn[ib[j] + kx];
                    #pragma unroll
                    for (int c=0;c<8;c++) acc[j][c] += iv*wv[c];
                }
            }
        }
    }

    #pragma unroll
    for (int c=0;c<8;c++){
        int co = co0 + co_slot + 8*c;
        #pragma unroll
        for (int j=0;j<5;j++)
            g_u[((b*C2 + co)*H2 + (y0 + Y[j]))*W2 + X[j]] = acc[j][c];
    }
}

// ============================================================
// squash on u: vectors of 32 consecutive floats; one warp per vector
// ============================================================
__global__ void squash_kernel(){
    int vec  = blockIdx.x*8 + (threadIdx.x >> 5);   // 102400 vectors
    int lane = threadIdx.x & 31;
    float val = g_u[vec*32 + lane];
    float sq = val*val;
    #pragma unroll
    for (int off=16; off; off>>=1) sq += __shfl_xor_sync(0xffffffffu, sq, off);
    float scale = sq / ((1.f + sq) * sqrtf(sq));
    g_u[vec*32 + lane] = val*scale;
}

// ============================================================
// u_hat[b][r][c] = sum_i W[r][c][0][i] * u[b][r][i]
// thread per (r,c), loops 8 batches (W row stays in registers)
// ============================================================
__global__ void uhat_kernel(const float* __restrict__ W){
    int idx = blockIdx.x*256 + threadIdx.x;   // 128000 = r*10 + c
    if (idx >= NR*NC) return;
    int r = idx / 10;
    float wv[32];
    const float4* wp = (const float4*)(W + (long long)idx*32);
    #pragma unroll
    for (int q=0;q<8;q++){
        float4 t = wp[q];
        wv[q*4]=t.x; wv[q*4+1]=t.y; wv[q*4+2]=t.z; wv[q*4+3]=t.w;
    }
    #pragma unroll
    for (int b=0;b<8;b++){
        const float4* up = (const float4*)(g_u + ((long long)b*NR + r)*32);
        float s = 0.f;
        #pragma unroll
        for (int q=0;q<8;q++){
            float4 t = up[q];
            s += wv[q*4]*t.x + wv[q*4+1]*t.y + wv[q*4+2]*t.z + wv[q*4+3]*t.w;
        }
        g_uhat[b*NR*NC + idx] = s;
    }
}

__global__ void zero_bij(){
    int i = blockIdx.x*256 + threadIdx.x;
    if (i < NR*NC) g_bij[i] = 0.f;
}

// ============================================================
// routing step: per class c, softmax over r of b_ij, s[b]=sum_r c_ij*uhat,
// v = scalar squash of s. One block per class.
// ============================================================
__global__ void route_s_kernel(float* __restrict__ dout, int final_it){
    int c = blockIdx.x;
    int t = threadIdx.x;
    __shared__ float sred[9][256];

    float m = -1e30f;
    for (int r=t; r<NR; r+=256) m = fmaxf(m, g_bij[r*10 + c]);
    sred[0][t] = m; __syncthreads();
    for (int off=128; off; off>>=1){
        if (t < off) sred[0][t] = fmaxf(sred[0][t], sred[0][t+off]);
        __syncthreads();
    }
    m = sred[0][0];
    __syncthreads();

    float Z = 0.f, s[8] = {0,0,0,0,0,0,0,0};
    for (int r=t; r<NR; r+=256){
        float e = expf(g_bij[r*10 + c] - m);
        Z += e;
        const float* up = g_uhat + r*10 + c;
        #pragma unroll
        for (int b=0;b<8;b++) s[b] += e * up[b*128000];
    }
    sred[0][t] = Z;
    #pragma unroll
    for (int b=0;b<8;b++) sred[1+b][t] = s[b];
    __syncthreads();
    for (int off=128; off; off>>=1){
        if (t < off){
            #pragma unroll
            for (int q=0;q<9;q++) sred[q][t] += sred[q][t+off];
        }
        __syncthreads();
    }
    if (t < 8){
        float sv = sred[1+t][0] / sred[0][0];
        float sn = sv*sv;
        float v = sn*sv / ((1.f + sn) * sqrtf(sn));
        g_v[t*10 + c] = v;
        if (final_it) dout[t*10 + c] = v;
    }
}

__global__ void route_update_kernel(){
    int idx = blockIdx.x*256 + threadIdx.x;   // r*10+c
    if (idx >= NR*NC) return;
    int c = idx % 10;
    float a = 0.f;
    #pragma unroll
    for (int b=0;b<8;b++) a += g_uhat[b*128000 + idx] * g_v[b*10 + c];
    g_bij[idx] += a;
}

// ============================================================
// decoder
// ============================================================
__global__ void dec1_kernel(const float* __restrict__ w1, const float* __restrict__ b1){
    int idx = blockIdx.x*256 + threadIdx.x;   // 4096
    int b = idx >> 9, j = idx & 511;
    float acc = b1[j];
    #pragma unroll
    for (int i=0;i<10;i++) acc += g_v[b*10 + i] * w1[i*512 + j];
    g_t1[idx] = fmaxf(acc, 0.f);
}

__global__ void dec2_kernel(const float* __restrict__ w2, const float* __restrict__ b2){
    __shared__ float sR[512];
    int j = blockIdx.x*256 + threadIdx.x;
    int b = blockIdx.y;
    for (int i=threadIdx.x; i<512; i+=256) sR[i] = g_t1[b*512 + i];
    __syncthreads();
    float acc = b2[j];
    for (int k=0;k<512;k++) acc += sR[k] * w2[k*1024 + j];
    g_t2[b*1024 + j] = fmaxf(acc, 0.f);
}

__global__ void dec3_kernel(const float* __restrict__ w3, const float* __restrict__ b3,
                            float* __restrict__ out){
    __shared__ float sRt[1024*8];   // r2 transposed [k][b], 32KB
    int tid = threadIdx.x;
    int n = blockIdx.x*256 + tid;   // 27648 = 108*256
    for (int i=tid; i<8192; i+=256){ int k = i>>3, b = i&7; sRt[i] = g_t2[b*1024 + k]; }
    __syncthreads();
    float acc[8];
    #pragma unroll
    for (int b=0;b<8;b++) acc[b] = 0.f;
    for (int k=0;k<1024;k++){
        float wv = w3[(long long)k*27648 + n];
        const float4* rp = (const float4*)(sRt + k*8);
        float4 a0 = rp[0], a1 = rp[1];
        acc[0] += wv*a0.x; acc[1] += wv*a0.y; acc[2] += wv*a0.z; acc[3] += wv*a0.w;
        acc[4] += wv*a1.x; acc[5] += wv*a1.y; acc[6] += wv*a1.z; acc[7] += wv*a1.w;
    }
    float bv = b3[n];
    #pragma unroll
    for (int b=0;b<8;b++){
        float z = acc[b] + bv;
        out[80 + b*27648 + n] = 1.f / (1.f + expf(-z));
    }
}

// ============================================================
extern "C" void kernel_launch(void* const* d_in, const int* in_sizes, int n_in,
                              void* d_out, int out_size){
    (void)in_sizes; (void)n_in; (void)out_size;
    const float* x   = (const float*)d_in[0];
    const float* c1w = (const float*)d_in[1];
    const float* c1b = (const float*)d_in[2];
    const float* pw  = (const float*)d_in[3];
    const float* pb  = (const float*)d_in[4];
    const float* dW  = (const float*)d_in[5];
    const float* w1  = (const float*)d_in[6];
    const float* b1  = (const float*)d_in[7];
    const float* w2  = (const float*)d_in[8];
    const float* b2  = (const float*)d_in[9];
    const float* w3  = (const float*)d_in[10];
    const float* b3  = (const float*)d_in[11];
    float* out = (float*)d_out;

    conv1_kernel<<<dim3(128,11,8), dim3(88,2)>>>(x, c1w, c1b);
    prim_kernel<<<dim3(10,4,8), 256>>>(pw, pb);
    squash_kernel<<<12800, 256>>>();
    uhat_kernel<<<500, 256>>>(dW);
    zero_bij<<<500, 256>>>();
    for (int it=0; it<3; it++){
        route_s_kernel<<<10, 256>>>(out, it==2 ? 1 : 0);
        if (it < 2) route_update_kernel<<<500, 256>>>();
    }
    dec1_kernel<<<16, 256>>>(w1, b1);
    dec2_kernel<<<dim3(4,8), 256>>>(w2, b2);
    dec3_kernel<<<108, 256>>>(w3, b3, out);
}

// round 4
// speedup vs baseline: 1.0448x; 1.0448x over previous
#include <cuda_runtime.h>
#include <math.h>

#define B 8
#define C1 256
#define H1 88
#define W1 88
#define C2 256
#define H2 40
#define W2 40
#define NR 12800
#define NC 10

// ---- device scratch (no allocations allowed) ----
__device__ float g_h[B*C1*H1*W1];      // conv1 output (relu'd)   63.4 MB
__device__ float g_u[B*C2*H2*W2];      // prim conv out / squashed u
__device__ float g_uhat[B*NR*NC];      // u_hat[b][r][c]
__device__ float g_bij[NR*NC];         // routing logits
__device__ float g_v[B*NC];            // v[b][c]
__device__ float g_t1[B*512];
__device__ float g_t2[B*1024];

// ============================================================
// conv1: x(8,3,96,96) * w(256,3,9,9) stride1 VALID -> relu -> h(8,256,88,88)
// block: (88,2)=176 thr; each thread: 4 rows x 2 c_out = 8 accumulators
// ============================================================
__global__ void conv1_kernel(const float* __restrict__ x,
                             const float* __restrict__ w,
                             const float* __restrict__ bias){
    __shared__ float sW[486];          // 2 c_out x 3 ci x 81
    __shared__ float sIn[3*16*96];     // 3 ch x 16 rows x 96 cols
    int tx = threadIdx.x, ty = threadIdx.y;
    int tid = ty*88 + tx;
    int co0 = blockIdx.x*2;
    int y0  = blockIdx.y*8;
    int b   = blockIdx.z;

    for (int i = tid; i < 486; i += 176) sW[i] = w[co0*243 + i];
    for (int i = tid; i < 4608; i += 176){
        int ci = i / 1536, rem = i % 1536;
        int row = rem / 96, col = rem % 96;
        sIn[i] = x[((b*3+ci)*96 + (y0+row))*96 + col];
    }
    __syncthreads();

    float acc0[4], acc1[4];
    float b0 = bias[co0], b1 = bias[co0+1];
    #pragma unroll
    for (int r=0;r<4;r++){ acc0[r]=b0; acc1[r]=b1; }

    for (int ci=0; ci<3; ci++){
        for (int ky=0; ky<9; ky++){
            #pragma unroll
            for (int kx=0; kx<9; kx++){
                float w0 = sW[      ci*81 + ky*9 + kx];
                float w1 = sW[243 + ci*81 + ky*9 + kx];
                #pragma unroll
                for (int r=0;r<4;r++){
                    float iv = sIn[ci*1536 + (ty*4 + r + ky)*96 + tx + kx];
                    acc0[r] += w0*iv;
                    acc1[r] += w1*iv;
                }
            }
        }
    }
    #pragma unroll
    for (int r=0;r<4;r++){
        int y = y0 + ty*4 + r;
        g_h[((b*C1+co0  )*H1 + y)*W1 + tx] = fmaxf(acc0[r], 0.f);
        g_h[((b*C1+co0+1)*H1 + y)*W1 + tx] = fmaxf(acc1[r], 0.f);
    }
}

// ============================================================
// prim conv: h(8,256,88,88) * w(256,256,9,9) stride2 VALID -> u(8,256,40,40)
// block: 256 thr, tile = 64 c_out x (40 x 4) positions
// thread: 5 positions x 8 c_out = 40 accumulators; 13 LDS per 40 FMA
// ============================================================
__global__ void prim_kernel(const float* __restrict__ w,
                            const float* __restrict__ bias){
    __shared__ float sW[64*81];   // 20.7 KB
    __shared__ float sIn[15*88];  // 5.3 KB  (15 input rows, full 88 width)
    int tid   = threadIdx.x;
    int ytile = blockIdx.x;       // 0..9
    int cog   = blockIdx.y;       // 0..3
    int b     = blockIdx.z;       // 0..7
    int co0 = cog*64;
    int y0  = ytile*4;
    int pos_slot = tid >> 3;      // 0..31
    int co_slot  = tid & 7;       // 0..7

    int X[5], Y[5];
    #pragma unroll
    for (int j=0;j<5;j++){ int p = pos_slot + 32*j; X[j] = p % 40; Y[j] = p / 40; }

    float acc[5][8];
    #pragma unroll
    for (int c=0;c<8;c++){
        float bv = bias[co0 + co_slot + 8*c];
        #pragma unroll
        for (int j=0;j<5;j++) acc[j][c] = bv;
    }

    for (int ci=0; ci<256; ci++){
        __syncthreads();
        for (int i = tid; i < 64*81; i += 256){
            int c = i / 81, k = i % 81;
            sW[i] = w[((co0 + c)*256 + ci)*81 + k];
        }
        const float* hp = g_h + ((b*C1 + ci)*H1 + y0*2)*W1;  // 15 contiguous rows
        for (int i = tid; i < 15*88; i += 256) sIn[i] = hp[i];
        __syncthreads();

        for (int ky=0; ky<9; ky++){
            int ib[5];
            #pragma unroll
            for (int j=0;j<5;j++) ib[j] = (Y[j]*2 + ky)*88 + X[j]*2;
            #pragma unroll
            for (int kx=0; kx<9; kx++){
                float wv[8];
                #pragma unroll
                for (int c=0;c<8;c++) wv[c] = sW[(co_slot + 8*c)*81 + ky*9 + kx];
                #pragma unroll
                for (int j=0;j<5;j++){
                    float iv = sIn[ib[j] + kx];
                    #pragma unroll
                    for (int c=0;c<8;c++) acc[j][c] += iv*wv[c];
                }
            }
        }
    }

    #pragma unroll
    for (int c=0;c<8;c++){
        int co = co0 + co_slot + 8*c;
        #pragma unroll
        for (int j=0;j<5;j++)
            g_u[((b*C2 + co)*H2 + (y0 + Y[j]))*W2 + X[j]] = acc[j][c];
    }
}

// ============================================================
// squash on u: vectors of 32 consecutive floats; one warp per vector
// ============================================================
__global__ void squash_kernel(){
    int vec  = blockIdx.x*8 + (threadIdx.x >> 5);   // 102400 vectors
    int lane = threadIdx.x & 31;
    float val = g_u[vec*32 + lane];
    float sq = val*val;
    #pragma unroll
    for (int off=16; off; off>>=1) sq += __shfl_xor_sync(0xffffffffu, sq, off);
    float scale = sq / ((1.f + sq) * sqrtf(sq));
    g_u[vec*32 + lane] = val*scale;
}

// ============================================================
// u_hat[b][r][c] = sum_i W[r][c][0][i] * u[b][r][i]
// thread per (r,c), loops 8 batches (W row stays in registers)
// ============================================================
__global__ void uhat_kernel(const float* __restrict__ W){
    int idx = blockIdx.x*256 + threadIdx.x;   // 128000 = r*10 + c
    if (idx >= NR*NC) return;
    int r = idx / 10;
    float wv[32];
    const float4* wp = (const float4*)(W + (long long)idx*32);
    #pragma unroll
    for (int q=0;q<8;q++){
        float4 t = wp[q];
        wv[q*4]=t.x; wv[q*4+1]=t.y; wv[q*4+2]=t.z; wv[q*4+3]=t.w;
    }
    #pragma unroll
    for (int b=0;b<8;b++){
        const float4* up = (const float4*)(g_u + ((long long)b*NR + r)*32);
        float s = 0.f;
        #pragma unroll
        for (int q=0;q<8;q++){
            float4 t = up[q];
            s += wv[q*4]*t.x + wv[q*4+1]*t.y + wv[q*4+2]*t.z + wv[q*4+3]*t.w;
        }
        g_uhat[b*NR*NC + idx] = s;
    }
}

__global__ void zero_bij(){
    int i = blockIdx.x*256 + threadIdx.x;
    if (i < NR*NC) g_bij[i] = 0.f;
}

// ============================================================
// routing step: per class c, softmax over r of b_ij, s[b]=sum_r c_ij*uhat,
// v = scalar squash of s. One block per class.
// ============================================================
__global__ void route_s_kernel(float* __restrict__ dout, int final_it){
    int c = blockIdx.x;
    int t = threadIdx.x;
    __shared__ float sred[9][256];

    float m = -1e30f;
    for (int r=t; r<NR; r+=256) m = fmaxf(m, g_bij[r*10 + c]);
    sred[0][t] = m; __syncthreads();
    for (int off=128; off; off>>=1){
        if (t < off) sred[0][t] = fmaxf(sred[0][t], sred[0][t+off]);
        __syncthreads();
    }
    m = sred[0][0];
    __syncthreads();

    float Z = 0.f, s[8] = {0,0,0,0,0,0,0,0};
    for (int r=t; r<NR; r+=256){
        float e = expf(g_bij[r*10 + c] - m);
        Z += e;
        const float* up = g_uhat + r*10 + c;
        #pragma unroll
        for (int b=0;b<8;b++) s[b] += e * up[b*128000];
    }
    sred[0][t] = Z;
    #pragma unroll
    for (int b=0;b<8;b++) sred[1+b][t] = s[b];
    __syncthreads();
    for (int off=128; off; off>>=1){
        if (t < off){
            #pragma unroll
            for (int q=0;q<9;q++) sred[q][t] += sred[q][t+off];
        }
        __syncthreads();
    }
    if (t < 8){
        float sv = sred[1+t][0] / sred[0][0];
        float sn = sv*sv;
        float v = sn*sv / ((1.f + sn) * sqrtf(sn));
        g_v[t*10 + c] = v;
        if (final_it) dout[t*10 + c] = v;
    }
}

__global__ void route_update_kernel(){
    int idx = blockIdx.x*256 + threadIdx.x;   // r*10+c
    if (idx >= NR*NC) return;
    int c = idx % 10;
    float a = 0.f;
    #pragma unroll
    for (int b=0;b<8;b++) a += g_uhat[b*128000 + idx] * g_v[b*10 + c];
    g_bij[idx] += a;
}

// ============================================================
// decoder
// ============================================================
__global__ void dec1_kernel(const float* __restrict__ w1, const float* __restrict__ b1){
    int idx = blockIdx.x*256 + threadIdx.x;   // 4096
    int b = idx >> 9, j = idx & 511;
    float acc = b1[j];
    #pragma unroll
    for (int i=0;i<10;i++) acc += g_v[b*10 + i] * w1[i*512 + j];
    g_t1[idx] = fmaxf(acc, 0.f);
}

__global__ void dec2_kernel(const float* __restrict__ w2, const float* __restrict__ b2){
    __shared__ float sR[512];
    int j = blockIdx.x*256 + threadIdx.x;
    int b = blockIdx.y;
    for (int i=threadIdx.x; i<512; i+=256) sR[i] = g_t1[b*512 + i];
    __syncthreads();
    float acc = b2[j];
    for (int k=0;k<512;k++) acc += sR[k] * w2[k*1024 + j];
    g_t2[b*1024 + j] = fmaxf(acc, 0.f);
}

__global__ void dec3_kernel(const float* __restrict__ w3, const float* __restrict__ b3,
                            float* __restrict__ out){
    __shared__ float sRt[1024*8];   // r2 transposed [k][b], 32KB
    int tid = threadIdx.x;
    int n = blockIdx.x*256 + tid;   // 27648 = 108*256
    for (int i=tid; i<8192; i+=256){ int k = i>>3, b = i&7; sRt[i] = g_t2[b*1024 + k]; }
    __syncthreads();
    float acc[8];
    #pragma unroll
    for (int b=0;b<8;b++) acc[b] = 0.f;
    for (int k=0;k<1024;k++){
        float wv = w3[(long long)k*27648 + n];
        const float4* rp = (const float4*)(sRt + k*8);
        float4 a0 = rp[0], a1 = rp[1];
        acc[0] += wv*a0.x; acc[1] += wv*a0.y; acc[2] += wv*a0.z; acc[3] += wv*a0.w;
        acc[4] += wv*a1.x; acc[5] += wv*a1.y; acc[6] += wv*a1.z; acc[7] += wv*a1.w;
    }
    float bv = b3[n];
    #pragma unroll
    for (int b=0;b<8;b++){
        float z = acc[b] + bv;
        out[80 + b*27648 + n] = 1.f / (1.f + expf(-z));
    }
}

// ============================================================
extern "C" void kernel_launch(void* const* d_in, const int* in_sizes, int n_in,
                              void* d_out, int out_size){
    (void)in_sizes; (void)n_in; (void)out_size;
    const float* x   = (const float*)d_in[0];
    const float* c1w = (const float*)d_in[1];
    const float* c1b = (const float*)d_in[2];
    const float* pw  = (const float*)d_in[3];
    const float* pb  = (const float*)d_in[4];
    const float* dW  = (const float*)d_in[5];
    const float* w1  = (const float*)d_in[6];
    const float* b1  = (const float*)d_in[7];
    const float* w2  = (const float*)d_in[8];
    const float* b2  = (const float*)d_in[9];
    const float* w3  = (const float*)d_in[10];
    const float* b3  = (const float*)d_in[11];
    float* out = (float*)d_out;

    conv1_kernel<<<dim3(128,11,8), dim3(88,2)>>>(x, c1w, c1b);
    prim_kernel<<<dim3(10,4,8), 256>>>(pw, pb);
    squash_kernel<<<12800, 256>>>();
    uhat_kernel<<<500, 256>>>(dW);
    zero_bij<<<500, 256>>>();
    for (int it=0; it<3; it++){
        route_s_kernel<<<10, 256>>>(out, it==2 ? 1 : 0);
        if (it < 2) route_update_kernel<<<500, 256>>>();
    }
    dec1_kernel<<<16, 256>>>(w1, b1);
    dec2_kernel<<<dim3(4,8), 256>>>(w2, b2);
    dec3_kernel<<<108, 256>>>(w3, b3, out);
}

// round 5
// speedup vs baseline: 2.2146x; 2.1197x over previous
#include <cuda_runtime.h>
#include <math.h>
#include <stdint.h>

#define B 8
#define C1 256
#define H1 88
#define W1 88
#define C2 256
#define H2 40
#define W2 40
#define NR 12800
#define NC 10

// ---- device scratch (no allocations allowed) ----
__device__ float g_h[B*C1*H1*W1];      // conv1 output (relu'd)   63.4 MB
__device__ float g_u[B*C2*H2*W2];      // prim conv out / squashed u
__device__ float g_uhat[B*NR*NC];      // u_hat[b][r][c]
__device__ float g_bij[NR*NC];         // routing logits
__device__ float g_v[B*NC];            // v[b][c]
__device__ float g_t1[B*512];
__device__ float g_t2[B*1024];

// ============================================================
// conv1: x(8,3,96,96) * w(256,3,9,9) stride1 VALID -> relu -> h(8,256,88,88)
// ============================================================
__global__ void conv1_kernel(const float* __restrict__ x,
                             const float* __restrict__ w,
                             const float* __restrict__ bias){
    __shared__ float sW[486];
    __shared__ float sIn[3*16*96];
    int tx = threadIdx.x, ty = threadIdx.y;
    int tid = ty*88 + tx;
    int co0 = blockIdx.x*2;
    int y0  = blockIdx.y*8;
    int b   = blockIdx.z;

    for (int i = tid; i < 486; i += 176) sW[i] = w[co0*243 + i];
    for (int i = tid; i < 4608; i += 176){
        int ci = i / 1536, rem = i % 1536;
        int row = rem / 96, col = rem % 96;
        sIn[i] = x[((b*3+ci)*96 + (y0+row))*96 + col];
    }
    __syncthreads();

    float acc0[4], acc1[4];
    float b0 = bias[co0], b1 = bias[co0+1];
    #pragma unroll
    for (int r=0;r<4;r++){ acc0[r]=b0; acc1[r]=b1; }

    for (int ci=0; ci<3; ci++){
        for (int ky=0; ky<9; ky++){
            #pragma unroll
            for (int kx=0; kx<9; kx++){
                float w0 = sW[      ci*81 + ky*9 + kx];
                float w1 = sW[243 + ci*81 + ky*9 + kx];
                #pragma unroll
                for (int r=0;r<4;r++){
                    float iv = sIn[ci*1536 + (ty*4 + r + ky)*96 + tx + kx];
                    acc0[r] += w0*iv;
                    acc1[r] += w1*iv;
                }
            }
        }
    }
    #pragma unroll
    for (int r=0;r<4;r++){
        int y = y0 + ty*4 + r;
        g_h[((b*C1+co0  )*H1 + y)*W1 + tx] = fmaxf(acc0[r], 0.f);
        g_h[((b*C1+co0+1)*H1 + y)*W1 + tx] = fmaxf(acc1[r], 0.f);
    }
}

// ============================================================
// prim conv as implicit GEMM on tensor cores (tf32 mma.sync):
//   C[cout=256][n=12800] = sum_{k=0..20735} W[cout][k] * Im[k][n]
//   k = ci*81 + ky*9 + kx ;  n = b*1600 + y*40 + x
//   Im[k][n] = g_h[b][ci][2y+ky][2x+kx]
// BM=128 BN=128 BK=32, 8 warps, warp tile 64x32 (4x4 grid of m16n8k8)
// ============================================================
__device__ __forceinline__ uint32_t f2tf32(float f){
    uint32_t r;
    asm("cvt.rna.tf32.f32 %0, %1;" : "=r"(r) : "f"(f));
    return r;
}

__global__ __launch_bounds__(256, 2)
void prim_mma_kernel(const float* __restrict__ w,
                     const float* __restrict__ bias){
    __shared__ float sA[32][136];   // [k][m]  (stride 136 => 8 mod 32: conflict-free frags)
    __shared__ float sB[32][136];   // [k][n]
    const float* __restrict__ h = g_h;

    int tid   = threadIdx.x;
    int mtile = blockIdx.x & 1;     // 0..1
    int ntile = blockIdx.x >> 1;    // 0..99
    int co0 = mtile*128;
    int n0  = ntile*128;

    // --- B gather mapping: thread handles k-row kk, 16 consecutive n ---
    int kk = tid >> 3;              // 0..31
    int jb = (tid & 7) * 16;        // n_local base
    int offn[16];
    #pragma unroll
    for (int j=0;j<16;j++){
        int n = n0 + jb + j;
        int bb = n / 1600, p = n % 1600;
        int y = p / 40, x = p % 40;
        offn[j] = ((bb*256)*88 + 2*y)*88 + 2*x;   // ci=ky=kx=0 base
    }

    // --- A load mapping: thread loads row (co0+am), 16 consecutive k ---
    int am = tid >> 1;
    int ak = (tid & 1) * 16;
    const float* wrow = w + (long long)(co0 + am)*20736 + ak;

    float acc[16][4];
    #pragma unroll
    for (int t=0;t<16;t++){
        #pragma unroll
        for (int q=0;q<4;q++) acc[t][q] = 0.f;
    }

    int warp = tid >> 5, lane = tid & 31;
    int wm = warp & 1;              // 0..1 -> 64 m-rows
    int wn = warp >> 1;             // 0..3 -> 32 n-cols
    int grp = lane >> 2, tig = lane & 3;

    for (int kt=0; kt<648; kt++){
        // global loads first (latency in flight)
        float av[16];
        const float4* ap = (const float4*)(wrow + kt*32);
        #pragma unroll
        for (int q=0;q<4;q++){
            float4 v = ap[q];
            av[q*4]=v.x; av[q*4+1]=v.y; av[q*4+2]=v.z; av[q*4+3]=v.w;
        }
        int kB = kt*32 + kk;
        int ci = kB / 81;
        int r  = kB - ci*81;
        int ky = r / 9;
        int kx = r - ky*9;
        int d  = ci*7744 + ky*88 + kx;
        float bv[16];
        #pragma unroll
        for (int j=0;j<16;j++) bv[j] = h[offn[j] + d];

        __syncthreads();   // previous iter's compute done
        #pragma unroll
        for (int q=0;q<16;q++)
            sA[ak + q][am] = __uint_as_float(f2tf32(av[q]));
        #pragma unroll
        for (int j=0;j<16;j++)
            sB[kk][jb + j] = __uint_as_float(f2tf32(bv[j]));
        __syncthreads();

        #pragma unroll
        for (int k8=0;k8<4;k8++){
            int kb = k8*8;
            uint32_t afr[4][4], bfr[4][2];
            #pragma unroll
            for (int ms=0;ms<4;ms++){
                int m = wm*64 + ms*16;
                afr[ms][0] = __float_as_uint(sA[kb+tig  ][m+grp  ]);
                afr[ms][1] = __float_as_uint(sA[kb+tig  ][m+grp+8]);
                afr[ms][2] = __float_as_uint(sA[kb+tig+4][m+grp  ]);
                afr[ms][3] = __float_as_uint(sA[kb+tig+4][m+grp+8]);
            }
            #pragma unroll
            for (int ns=0;ns<4;ns++){
                int nn = wn*32 + ns*8;
                bfr[ns][0] = __float_as_uint(sB[kb+tig  ][nn+grp]);
                bfr[ns][1] = __float_as_uint(sB[kb+tig+4][nn+grp]);
            }
            #pragma unroll
            for (int ms=0;ms<4;ms++){
                #pragma unroll
                for (int ns=0;ns<4;ns++){
                    float* c = acc[ms*4+ns];
                    asm volatile(
                        "mma.sync.aligned.m16n8k8.row.col.f32.tf32.tf32.f32 "
                        "{%0,%1,%2,%3}, {%4,%5,%6,%7}, {%8,%9}, {%0,%1,%2,%3};\n"
                        : "+f"(c[0]), "+f"(c[1]), "+f"(c[2]), "+f"(c[3])
                        : "r"(afr[ms][0]), "r"(afr[ms][1]),
                          "r"(afr[ms][2]), "r"(afr[ms][3]),
                          "r"(bfr[ns][0]), "r"(bfr[ns][1]));
                }
            }
        }
    }

    // epilogue: + bias, scatter to g_u[b][co][y][x] (p = y*40+x contiguous)
    #pragma unroll
    for (int ms=0;ms<4;ms++){
        int coA = co0 + wm*64 + ms*16 + grp;
        float bA = bias[coA];
        float bC = bias[coA + 8];
        #pragma unroll
        for (int ns=0;ns<4;ns++){
            int nb = n0 + wn*32 + ns*8 + 2*tig;
            float* c = acc[ms*4+ns];
            #pragma unroll
            for (int e=0;e<4;e++){
                int n  = nb + (e & 1);
                int co = coA + (e >> 1)*8;
                float bvv = (e >> 1) ? bC : bA;
                int bb = n / 1600, p = n % 1600;
                g_u[(bb*256 + co)*1600 + p] = c[e] + bvv;
            }
        }
    }
}

// ============================================================
// squash on u: vectors of 32 consecutive floats; one warp per vector
// ============================================================
__global__ void squash_kernel(){
    int vec  = blockIdx.x*8 + (threadIdx.x >> 5);
    int lane = threadIdx.x & 31;
    float val = g_u[vec*32 + lane];
    float sq = val*val;
    #pragma unroll
    for (int off=16; off; off>>=1) sq += __shfl_xor_sync(0xffffffffu, sq, off);
    float scale = sq / ((1.f + sq) * sqrtf(sq));
    g_u[vec*32 + lane] = val*scale;
}

// ============================================================
// u_hat[b][r][c] = sum_i W[r][c][0][i] * u[b][r][i]
// ============================================================
__global__ void uhat_kernel(const float* __restrict__ W){
    int idx = blockIdx.x*256 + threadIdx.x;
    if (idx >= NR*NC) return;
    int r = idx / 10;
    float wv[32];
    const float4* wp = (const float4*)(W + (long long)idx*32);
    #pragma unroll
    for (int q=0;q<8;q++){
        float4 t = wp[q];
        wv[q*4]=t.x; wv[q*4+1]=t.y; wv[q*4+2]=t.z; wv[q*4+3]=t.w;
    }
    #pragma unroll
    for (int b=0;b<8;b++){
        const float4* up = (const float4*)(g_u + ((long long)b*NR + r)*32);
        float s = 0.f;
        #pragma unroll
        for (int q=0;q<8;q++){
            float4 t = up[q];
            s += wv[q*4]*t.x + wv[q*4+1]*t.y + wv[q*4+2]*t.z + wv[q*4+3]*t.w;
        }
        g_uhat[b*NR*NC + idx] = s;
    }
}

__global__ void zero_bij(){
    int i = blockIdx.x*256 + threadIdx.x;
    if (i < NR*NC) g_bij[i] = 0.f;
}

// ============================================================
// routing step
// ============================================================
__global__ void route_s_kernel(float* __restrict__ dout, int final_it){
    int c = blockIdx.x;
    int t = threadIdx.x;
    __shared__ float sred[9][256];

    float m = -1e30f;
    for (int r=t; r<NR; r+=256) m = fmaxf(m, g_bij[r*10 + c]);
    sred[0][t] = m; __syncthreads();
    for (int off=128; off; off>>=1){
        if (t < off) sred[0][t] = fmaxf(sred[0][t], sred[0][t+off]);
        __syncthreads();
    }
    m = sred[0][0];
    __syncthreads();

    float Z = 0.f, s[8] = {0,0,0,0,0,0,0,0};
    for (int r=t; r<NR; r+=256){
        float e = expf(g_bij[r*10 + c] - m);
        Z += e;
        const float* up = g_uhat + r*10 + c;
        #pragma unroll
        for (int b=0;b<8;b++) s[b] += e * up[b*128000];
    }
    sred[0][t] = Z;
    #pragma unroll
    for (int b=0;b<8;b++) sred[1+b][t] = s[b];
    __syncthreads();
    for (int off=128; off; off>>=1){
        if (t < off){
            #pragma unroll
            for (int q=0;q<9;q++) sred[q][t] += sred[q][t+off];
        }
        __syncthreads();
    }
    if (t < 8){
        float sv = sred[1+t][0] / sred[0][0];
        float sn = sv*sv;
        float v = sn*sv / ((1.f + sn) * sqrtf(sn));
        g_v[t*10 + c] = v;
        if (final_it) dout[t*10 + c] = v;
    }
}

__global__ void route_update_kernel(){
    int idx = blockIdx.x*256 + threadIdx.x;
    if (idx >= NR*NC) return;
    int c = idx % 10;
    float a = 0.f;
    #pragma unroll
    for (int b=0;b<8;b++) a += g_uhat[b*128000 + idx] * g_v[b*10 + c];
    g_bij[idx] += a;
}

// ============================================================
// decoder
// ============================================================
__global__ void dec1_kernel(const float* __restrict__ w1, const float* __restrict__ b1){
    int idx = blockIdx.x*256 + threadIdx.x;
    int b = idx >> 9, j = idx & 511;
    float acc = b1[j];
    #pragma unroll
    for (int i=0;i<10;i++) acc += g_v[b*10 + i] * w1[i*512 + j];
    g_t1[idx] = fmaxf(acc, 0.f);
}

__global__ void dec2_kernel(const float* __restrict__ w2, const float* __restrict__ b2){
    __shared__ float sR[512];
    int j = blockIdx.x*256 + threadIdx.x;
    int b = blockIdx.y;
    for (int i=threadIdx.x; i<512; i+=256) sR[i] = g_t1[b*512 + i];
    __syncthreads();
    float acc = b2[j];
    for (int k=0;k<512;k++) acc += sR[k] * w2[k*1024 + j];
    g_t2[b*1024 + j] = fmaxf(acc, 0.f);
}

__global__ void dec3_kernel(const float* __restrict__ w3, const float* __restrict__ b3,
                            float* __restrict__ out){
    __shared__ float sRt[1024*8];
    int tid = threadIdx.x;
    int n = blockIdx.x*256 + tid;
    for (int i=tid; i<8192; i+=256){ int k = i>>3, b = i&7; sRt[i] = g_t2[b*1024 + k]; }
    __syncthreads();
    float acc[8];
    #pragma unroll
    for (int b=0;b<8;b++) acc[b] = 0.f;
    for (int k=0;k<1024;k++){
        float wv = w3[(long long)k*27648 + n];
        const float4* rp = (const float4*)(sRt + k*8);
        float4 a0 = rp[0], a1 = rp[1];
        acc[0] += wv*a0.x; acc[1] += wv*a0.y; acc[2] += wv*a0.z; acc[3] += wv*a0.w;
        acc[4] += wv*a1.x; acc[5] += wv*a1.y; acc[6] += wv*a1.z; acc[7] += wv*a1.w;
    }
    float bv = b3[n];
    #pragma unroll
    for (int b=0;b<8;b++){
        float z = acc[b] + bv;
        out[80 + b*27648 + n] = 1.f / (1.f + expf(-z));
    }
}

// ============================================================
extern "C" void kernel_launch(void* const* d_in, const int* in_sizes, int n_in,
                              void* d_out, int out_size){
    (void)in_sizes; (void)n_in; (void)out_size;
    const float* x   = (const float*)d_in[0];
    const float* c1w = (const float*)d_in[1];
    const float* c1b = (const float*)d_in[2];
    const float* pw  = (const float*)d_in[3];
    const float* pb  = (const float*)d_in[4];
    const float* dW  = (const float*)d_in[5];
    const float* w1  = (const float*)d_in[6];
    const float* b1  = (const float*)d_in[7];
    const float* w2  = (const float*)d_in[8];
    const float* b2  = (const float*)d_in[9];
    const float* w3  = (const float*)d_in[10];
    const float* b3  = (const float*)d_in[11];
    float* out = (float*)d_out;

    conv1_kernel<<<dim3(128,11,8), dim3(88,2)>>>(x, c1w, c1b);
    prim_mma_kernel<<<200, 256>>>(pw, pb);
    squash_kernel<<<12800, 256>>>();
    uhat_kernel<<<500, 256>>>(dW);
    zero_bij<<<500, 256>>>();
    for (int it=0; it<3; it++){
        route_s_kernel<<<10, 256>>>(out, it==2 ? 1 : 0);
        if (it < 2) route_update_kernel<<<500, 256>>>();
    }
    dec1_kernel<<<16, 256>>>(w1, b1);
    dec2_kernel<<<dim3(4,8), 256>>>(w2, b2);
    dec3_kernel<<<108, 256>>>(w3, b3, out);
}

// round 6
// speedup vs baseline: 2.4324x; 1.0984x over previous
#include <cuda_runtime.h>
#include <math.h>
#include <stdint.h>

#define B 8
#define C1 256
#define H1 88
#define W1 88
#define C2 256
#define H2 40
#define W2 40
#define NR 12800
#define NC 10

// ---- device scratch (no allocations allowed) ----
__device__ float g_h[B*C1*H1*W1];      // conv1 output (relu'd, tf32-rounded)
__device__ float g_wt[256*20736];      // prim weights, tf32-rounded
__device__ float g_acc[2*256*12800];   // split-K partial sums
__device__ float g_u[B*C2*H2*W2];      // squashed u
__device__ float g_uhat[B*NR*NC];
__device__ float g_bij[NR*NC];
__device__ float g_v[B*NC];
__device__ float g_t1[B*512];
__device__ float g_t2[B*1024];

__device__ __forceinline__ uint32_t f2tf32(float f){
    uint32_t r;
    asm("cvt.rna.tf32.f32 %0, %1;" : "=r"(r) : "f"(f));
    return r;
}
__device__ __forceinline__ void cpa16(uint32_t dst, const void* src){
    asm volatile("cp.async.cg.shared.global [%0], [%1], 16;\n" :: "r"(dst), "l"(src));
}
__device__ __forceinline__ void cpa4(uint32_t dst, const void* src){
    asm volatile("cp.async.ca.shared.global [%0], [%1], 4;\n" :: "r"(dst), "l"(src));
}
__device__ __forceinline__ uint32_t smem_u32(const void* p){
    uint32_t a;
    asm("{ .reg .u64 t; cvta.to.shared.u64 t, %1; cvt.u32.u64 %0, t; }" : "=r"(a) : "l"(p));
    return a;
}

// ============================================================
// tf32 pre-round of prim weights
// ============================================================
__global__ void wround_kernel(const float* __restrict__ w){
    int i = (blockIdx.x*256 + threadIdx.x)*4;
    float4 v = *(const float4*)(w + i);
    float4 o;
    o.x = __uint_as_float(f2tf32(v.x));
    o.y = __uint_as_float(f2tf32(v.y));
    o.z = __uint_as_float(f2tf32(v.z));
    o.w = __uint_as_float(f2tf32(v.w));
    *(float4*)(g_wt + i) = o;
}

// ============================================================
// conv1: x(8,3,96,96) * w(256,3,9,9) stride1 -> relu -> tf32-round -> g_h
// ============================================================
__global__ void conv1_kernel(const float* __restrict__ x,
                             const float* __restrict__ w,
                             const float* __restrict__ bias){
    __shared__ float sW[486];
    __shared__ float sIn[3*16*96];
    int tx = threadIdx.x, ty = threadIdx.y;
    int tid = ty*88 + tx;
    int co0 = blockIdx.x*2;
    int y0  = blockIdx.y*8;
    int b   = blockIdx.z;

    for (int i = tid; i < 486; i += 176) sW[i] = w[co0*243 + i];
    for (int i = tid; i < 4608; i += 176){
        int ci = i / 1536, rem = i % 1536;
        int row = rem / 96, col = rem % 96;
        sIn[i] = x[((b*3+ci)*96 + (y0+row))*96 + col];
    }
    __syncthreads();

    float acc0[4], acc1[4];
    float b0 = bias[co0], b1 = bias[co0+1];
    #pragma unroll
    for (int r=0;r<4;r++){ acc0[r]=b0; acc1[r]=b1; }

    for (int ci=0; ci<3; ci++){
        for (int ky=0; ky<9; ky++){
            #pragma unroll
            for (int kx=0; kx<9; kx++){
                float w0 = sW[      ci*81 + ky*9 + kx];
                float w1 = sW[243 + ci*81 + ky*9 + kx];
                #pragma unroll
                for (int r=0;r<4;r++){
                    float iv = sIn[ci*1536 + (ty*4 + r + ky)*96 + tx + kx];
                    acc0[r] += w0*iv;
                    acc1[r] += w1*iv;
                }
            }
        }
    }
    #pragma unroll
    for (int r=0;r<4;r++){
        int y = y0 + ty*4 + r;
        g_h[((b*C1+co0  )*H1 + y)*W1 + tx] = __uint_as_float(f2tf32(fmaxf(acc0[r], 0.f)));
        g_h[((b*C1+co0+1)*H1 + y)*W1 + tx] = __uint_as_float(f2tf32(fmaxf(acc1[r], 0.f)));
    }
}

// ============================================================
// prim conv implicit GEMM, tf32 mma, cp.async double-buffered, split-K=2
// C[256][12800], K=20736. BM=128 BN=128 BK=32, 8 warps (64x32 warp tiles)
// A smem [m][k] pad 36 ; B smem [k][n] pad 136
// ============================================================
#define KT_STEPS 324
#define SA_EL (128*36)
#define SB_EL (32*136)
#define STAGE_EL (SA_EL + SB_EL)

__global__ __launch_bounds__(256, 2)
void prim_mma_kernel(){
    extern __shared__ float sm[];
    uint32_t smb = smem_u32(sm);
    int tid   = threadIdx.x;
    int ntile = blockIdx.x;       // 0..99
    int mtile = blockIdx.y;       // 0..1
    int split = blockIdx.z;       // 0..1
    int co0 = mtile*128;
    int n0  = ntile*128;
    int koff = split*10368;

    // --- A async-load mapping: thread -> row (co0+am), 16 consecutive k ---
    int am = tid >> 1;
    int ak = (tid & 1) * 16;
    const float* wA = g_wt + (long long)(co0 + am)*20736 + koff + ak;
    uint32_t dA = smb + (uint32_t)(am*36 + ak)*4u;

    // --- B async-load mapping: thread -> k-row kk, 16 consecutive n ---
    int kk = tid >> 3;
    int jb = (tid & 7) * 16;
    int offn[16];
    #pragma unroll
    for (int j=0;j<16;j++){
        int n = n0 + jb + j;
        int bb = n / 1600, p = n % 1600;
        int y = p / 40, xx = p % 40;
        offn[j] = ((bb*256)*88 + 2*y)*88 + 2*xx;
    }
    uint32_t dB = smb + (uint32_t)(SA_EL + kk*136 + jb)*4u;

    float acc[16][4];
    #pragma unroll
    for (int t=0;t<16;t++){
        #pragma unroll
        for (int q=0;q<4;q++) acc[t][q] = 0.f;
    }

    int warp = tid >> 5, lane = tid & 31;
    int wm = warp & 1;
    int wn = warp >> 1;
    int grp = lane >> 2, tig = lane & 3;

    // issue async loads for k-tile kt into stage kt&1
    auto issue = [&](int kt){
        uint32_t so = (uint32_t)((kt & 1) * STAGE_EL) * 4u;
        const float* a = wA + kt*32;
        cpa16(dA + so,      a);
        cpa16(dA + so + 16, a + 4);
        cpa16(dA + so + 32, a + 8);
        cpa16(dA + so + 48, a + 12);
        int kB = koff + kt*32 + kk;
        int ci = kB / 81;
        int r  = kB - ci*81;
        int ky = r / 9;
        int kx = r - ky*9;
        const float* bsrc = g_h + ci*7744 + ky*88 + kx;
        uint32_t sb = dB + so;
        #pragma unroll
        for (int j=0;j<16;j++) cpa4(sb + j*4u, bsrc + offn[j]);
    };

    issue(0);
    asm volatile("cp.async.commit_group;\n");

    for (int kt=0; kt<KT_STEPS; kt++){
        if (kt+1 < KT_STEPS){
            issue(kt+1);
            asm volatile("cp.async.commit_group;\n");
            asm volatile("cp.async.wait_group 1;\n");
        } else {
            asm volatile("cp.async.wait_group 0;\n");
        }
        __syncthreads();

        const float* sA = sm + (kt & 1)*STAGE_EL;
        const float* sB = sA + SA_EL;

        #pragma unroll
        for (int k8=0;k8<4;k8++){
            int kb = k8*8;
            uint32_t afr[4][4], bfr[4][2];
            #pragma unroll
            for (int ms=0;ms<4;ms++){
                int m = wm*64 + ms*16;
                afr[ms][0] = __float_as_uint(sA[(m+grp  )*36 + kb+tig  ]);
                afr[ms][1] = __float_as_uint(sA[(m+grp+8)*36 + kb+tig  ]);
                afr[ms][2] = __float_as_uint(sA[(m+grp  )*36 + kb+tig+4]);
                afr[ms][3] = __float_as_uint(sA[(m+grp+8)*36 + kb+tig+4]);
            }
            #pragma unroll
            for (int ns=0;ns<4;ns++){
                int nn = wn*32 + ns*8;
                bfr[ns][0] = __float_as_uint(sB[(kb+tig  )*136 + nn+grp]);
                bfr[ns][1] = __float_as_uint(sB[(kb+tig+4)*136 + nn+grp]);
            }
            #pragma unroll
            for (int ms=0;ms<4;ms++){
                #pragma unroll
                for (int ns=0;ns<4;ns++){
                    float* c = acc[ms*4+ns];
                    asm volatile(
                        "mma.sync.aligned.m16n8k8.row.col.f32.tf32.tf32.f32 "
                        "{%0,%1,%2,%3}, {%4,%5,%6,%7}, {%8,%9}, {%0,%1,%2,%3};\n"
                        : "+f"(c[0]), "+f"(c[1]), "+f"(c[2]), "+f"(c[3])
                        : "r"(afr[ms][0]), "r"(afr[ms][1]),
                          "r"(afr[ms][2]), "r"(afr[ms][3]),
                          "r"(bfr[ns][0]), "r"(bfr[ns][1]));
                }
            }
        }
        __syncthreads();
    }

    // epilogue: raw partials to g_acc[split][co][n]
    float* dst = g_acc + (size_t)split * (256*12800);
    #pragma unroll
    for (int ms=0;ms<4;ms++){
        int coA = co0 + wm*64 + ms*16 + grp;
        #pragma unroll
        for (int ns=0;ns<4;ns++){
            int nb = n0 + wn*32 + ns*8 + 2*tig;
            float* c = acc[ms*4+ns];
            #pragma unroll
            for (int e=0;e<4;e++){
                int n  = nb + (e & 1);
                int co = coA + (e >> 1)*8;
                dst[(size_t)co*12800 + n] = c[e];
            }
        }
    }
}

// ============================================================
// combine split-K partials + bias, then squash -> g_u
// one warp per 32-elem capsule vector
// ============================================================
__global__ void combine_squash_kernel(const float* __restrict__ bias){
    int vec  = blockIdx.x*8 + (threadIdx.x >> 5);   // 102400
    int lane = threadIdx.x & 31;
    int b  = vec / 12800;
    int rem = vec % 12800;
    int co = rem / 50;
    int j  = rem % 50;
    int n  = b*1600 + j*32 + lane;
    size_t ai = (size_t)co*12800 + n;
    float val = g_acc[ai] + g_acc[ai + 256*12800] + bias[co];
    float sq = val*val;
    #pragma unroll
    for (int off=16; off; off>>=1) sq += __shfl_xor_sync(0xffffffffu, sq, off);
    float scale = sq / ((1.f + sq) * sqrtf(sq));
    g_u[((size_t)(b*256 + co))*1600 + j*32 + lane] = val*scale;
}

// ============================================================
// u_hat[b][r][c] = sum_i W[r][c][0][i] * u[b][r][i]
// ============================================================
__global__ void uhat_kernel(const float* __restrict__ W){
    int idx = blockIdx.x*256 + threadIdx.x;
    if (idx >= NR*NC) return;
    int r = idx / 10;
    float wv[32];
    const float4* wp = (const float4*)(W + (long long)idx*32);
    #pragma unroll
    for (int q=0;q<8;q++){
        float4 t = wp[q];
        wv[q*4]=t.x; wv[q*4+1]=t.y; wv[q*4+2]=t.z; wv[q*4+3]=t.w;
    }
    #pragma unroll
    for (int b=0;b<8;b++){
        const float4* up = (const float4*)(g_u + ((long long)b*NR + r)*32);
        float s = 0.f;
        #pragma unroll
        for (int q=0;q<8;q++){
            float4 t = up[q];
            s += wv[q*4]*t.x + wv[q*4+1]*t.y + wv[q*4+2]*t.z + wv[q*4+3]*t.w;
        }
        g_uhat[b*NR*NC + idx] = s;
    }
}

__global__ void zero_bij(){
    int i = blockIdx.x*256 + threadIdx.x;
    if (i < NR*NC) g_bij[i] = 0.f;
}

// ============================================================
// routing
// ============================================================
__global__ void route_s_kernel(float* __restrict__ dout, int final_it){
    int c = blockIdx.x;
    int t = threadIdx.x;
    __shared__ float sred[9][256];

    float m = -1e30f;
    for (int r=t; r<NR; r+=256) m = fmaxf(m, g_bij[r*10 + c]);
    sred[0][t] = m; __syncthreads();
    for (int off=128; off; off>>=1){
        if (t < off) sred[0][t] = fmaxf(sred[0][t], sred[0][t+off]);
        __syncthreads();
    }
    m = sred[0][0];
    __syncthreads();

    float Z = 0.f, s[8] = {0,0,0,0,0,0,0,0};
    for (int r=t; r<NR; r+=256){
        float e = expf(g_bij[r*10 + c] - m);
        Z += e;
        const float* up = g_uhat + r*10 + c;
        #pragma unroll
        for (int b=0;b<8;b++) s[b] += e * up[b*128000];
    }
    sred[0][t] = Z;
    #pragma unroll
    for (int b=0;b<8;b++) sred[1+b][t] = s[b];
    __syncthreads();
    for (int off=128; off; off>>=1){
        if (t < off){
            #pragma unroll
            for (int q=0;q<9;q++) sred[q][t] += sred[q][t+off];
        }
        __syncthreads();
    }
    if (t < 8){
        float sv = sred[1+t][0] / sred[0][0];
        float sn = sv*sv;
        float v = sn*sv / ((1.f + sn) * sqrtf(sn));
        g_v[t*10 + c] = v;
        if (final_it) dout[t*10 + c] = v;
    }
}

__global__ void route_update_kernel(){
    int idx = blockIdx.x*256 + threadIdx.x;
    if (idx >= NR*NC) return;
    int c = idx % 10;
    float a = 0.f;
    #pragma unroll
    for (int b=0;b<8;b++) a += g_uhat[b*128000 + idx] * g_v[b*10 + c];
    g_bij[idx] += a;
}

// ============================================================
// decoder
// ============================================================
__global__ void dec1_kernel(const float* __restrict__ w1, const float* __restrict__ b1){
    int idx = blockIdx.x*256 + threadIdx.x;
    int b = idx >> 9, j = idx & 511;
    float acc = b1[j];
    #pragma unroll
    for (int i=0;i<10;i++) acc += g_v[b*10 + i] * w1[i*512 + j];
    g_t1[idx] = fmaxf(acc, 0.f);
}

__global__ void dec2_kernel(const float* __restrict__ w2, const float* __restrict__ b2){
    __shared__ float sR[512];
    int j = blockIdx.x*256 + threadIdx.x;
    int b = blockIdx.y;
    for (int i=threadIdx.x; i<512; i+=256) sR[i] = g_t1[b*512 + i];
    __syncthreads();
    float acc = b2[j];
    for (int k=0;k<512;k++) acc += sR[k] * w2[k*1024 + j];
    g_t2[b*1024 + j] = fmaxf(acc, 0.f);
}

__global__ void dec3_kernel(const float* __restrict__ w3, const float* __restrict__ b3,
                            float* __restrict__ out){
    __shared__ float sRt[1024*8];
    int tid = threadIdx.x;
    int n = blockIdx.x*256 + tid;
    for (int i=tid; i<8192; i+=256){ int k = i>>3, b = i&7; sRt[i] = g_t2[b*1024 + k]; }
    __syncthreads();
    float acc[8];
    #pragma unroll
    for (int b=0;b<8;b++) acc[b] = 0.f;
    for (int k=0;k<1024;k++){
        float wv = w3[(long long)k*27648 + n];
        const float4* rp = (const float4*)(sRt + k*8);
        float4 a0 = rp[0], a1 = rp[1];
        acc[0] += wv*a0.x; acc[1] += wv*a0.y; acc[2] += wv*a0.z; acc[3] += wv*a0.w;
        acc[4] += wv*a1.x; acc[5] += wv*a1.y; acc[6] += wv*a1.z; acc[7] += wv*a1.w;
    }
    float bv = b3[n];
    #pragma unroll
    for (int b=0;b<8;b++){
        float z = acc[b] + bv;
        out[80 + b*27648 + n] = 1.f / (1.f + expf(-z));
    }
}

// ============================================================
extern "C" void kernel_launch(void* const* d_in, const int* in_sizes, int n_in,
                              void* d_out, int out_size){
    (void)in_sizes; (void)n_in; (void)out_size;
    const float* x   = (const float*)d_in[0];
    const float* c1w = (const float*)d_in[1];
    const float* c1b = (const float*)d_in[2];
    const float* pw  = (const float*)d_in[3];
    const float* pb  = (const float*)d_in[4];
    const float* dW  = (const float*)d_in[5];
    const float* w1  = (const float*)d_in[6];
    const float* b1  = (const float*)d_in[7];
    const float* w2  = (const float*)d_in[8];
    const float* b2  = (const float*)d_in[9];
    const float* w3  = (const float*)d_in[10];
    const float* b3  = (const float*)d_in[11];
    float* out = (float*)d_out;

    static int smem_set = 0;
    if (!smem_set){
        cudaFuncSetAttribute(prim_mma_kernel,
                             cudaFuncAttributeMaxDynamicSharedMemorySize,
                             2*STAGE_EL*4);
        smem_set = 1;
    }

    wround_kernel<<<5184, 256>>>(pw);
    conv1_kernel<<<dim3(128,11,8), dim3(88,2)>>>(x, c1w, c1b);
    prim_mma_kernel<<<dim3(100,2,2), 256, 2*STAGE_EL*4>>>();
    combine_squash_kernel<<<12800, 256>>>(pb);
    uhat_kernel<<<500, 256>>>(dW);
    zero_bij<<<500, 256>>>();
    for (int it=0; it<3; it++){
        route_s_kernel<<<10, 256>>>(out, it==2 ? 1 : 0);
        if (it < 2) route_update_kernel<<<500, 256>>>();
    }
    dec1_kernel<<<16, 256>>>(w1, b1);
    dec2_kernel<<<dim3(4,8), 256>>>(w2, b2);
    dec3_kernel<<<108, 256>>>(w3, b3, out);
}

// round 8
// speedup vs baseline: 3.0699x; 1.2621x over previous
#include <cuda_runtime.h>
#include <math.h>
#include <stdint.h>

#define B 8
#define C1 256
#define H1 88
#define W1 88
#define C2 256
#define H2 40
#define W2 40
#define NR 12800
#define NC 10

#define PSTR (8*256*88*44)   // parity-plane stride (elements)

// ---- device scratch (no allocations allowed) ----
__device__ float g_h2[2*PSTR];         // conv1 out, parity planes, tf32-rounded
__device__ float g_wt[256*20736];      // prim weights, tf32-rounded
__device__ float g_acc[2*256*12800];   // split-K partial sums
__device__ float g_u[B*C2*H2*W2];      // squashed u
__device__ float g_uhat[B*NR*NC];
__device__ float g_bij[NR*NC];
__device__ float g_v[B*NC];
__device__ float g_t1[B*512];
__device__ float g_t2[B*1024];

__device__ __forceinline__ uint32_t f2tf32(float f){
    uint32_t r;
    asm("cvt.rna.tf32.f32 %0, %1;" : "=r"(r) : "f"(f));
    return r;
}
__device__ __forceinline__ void cpa16(uint32_t dst, const void* src){
    asm volatile("cp.async.cg.shared.global [%0], [%1], 16;\n" :: "r"(dst), "l"(src));
}
__device__ __forceinline__ void cpa4(uint32_t dst, const void* src){
    asm volatile("cp.async.ca.shared.global [%0], [%1], 4;\n" :: "r"(dst), "l"(src));
}
__device__ __forceinline__ uint32_t smem_u32(const void* p){
    uint32_t a;
    asm("{ .reg .u64 t; cvta.to.shared.u64 t, %1; cvt.u32.u64 %0, t; }" : "=r"(a) : "l"(p));
    return a;
}

// ============================================================
// tf32 pre-round of prim weights
// ============================================================
__global__ void wround_kernel(const float* __restrict__ w){
    int i = (blockIdx.x*256 + threadIdx.x)*4;
    float4 v = *(const float4*)(w + i);
    float4 o;
    o.x = __uint_as_float(f2tf32(v.x));
    o.y = __uint_as_float(f2tf32(v.y));
    o.z = __uint_as_float(f2tf32(v.z));
    o.w = __uint_as_float(f2tf32(v.w));
    *(float4*)(g_wt + i) = o;
}

// ============================================================
// conv1: x(8,3,96,96) * w(256,3,9,9) stride1 -> relu -> tf32 -> parity planes
// g_h2[x&1][b][co][y][x>>1]
// ============================================================
__global__ void conv1_kernel(const float* __restrict__ x,
                             const float* __restrict__ w,
                             const float* __restrict__ bias){
    __shared__ float sW[486];
    __shared__ float sIn[3*16*96];
    int tx = threadIdx.x, ty = threadIdx.y;
    int tid = ty*88 + tx;
    int co0 = blockIdx.x*2;
    int y0  = blockIdx.y*8;
    int b   = blockIdx.z;

    for (int i = tid; i < 486; i += 176) sW[i] = w[co0*243 + i];
    for (int i = tid; i < 4608; i += 176){
        int ci = i / 1536, rem = i % 1536;
        int row = rem / 96, col = rem % 96;
        sIn[i] = x[((b*3+ci)*96 + (y0+row))*96 + col];
    }
    __syncthreads();

    float acc0[4], acc1[4];
    float b0 = bias[co0], b1 = bias[co0+1];
    #pragma unroll
    for (int r=0;r<4;r++){ acc0[r]=b0; acc1[r]=b1; }

    for (int ci=0; ci<3; ci++){
        for (int ky=0; ky<9; ky++){
            #pragma unroll
            for (int kx=0; kx<9; kx++){
                float w0 = sW[      ci*81 + ky*9 + kx];
                float w1 = sW[243 + ci*81 + ky*9 + kx];
                #pragma unroll
                for (int r=0;r<4;r++){
                    float iv = sIn[ci*1536 + (ty*4 + r + ky)*96 + tx + kx];
                    acc0[r] += w0*iv;
                    acc1[r] += w1*iv;
                }
            }
        }
    }
    int pl = (tx & 1)*PSTR + (tx >> 1);
    #pragma unroll
    for (int r=0;r<4;r++){
        int y = y0 + ty*4 + r;
        g_h2[pl + ((b*C1+co0  )*88 + y)*44] = __uint_as_float(f2tf32(fmaxf(acc0[r], 0.f)));
        g_h2[pl + ((b*C1+co0+1)*88 + y)*44] = __uint_as_float(f2tf32(fmaxf(acc1[r], 0.f)));
    }
}

// ============================================================
// prim conv implicit GEMM, tf32 mma, cp.async double-buffered, split-K=2
// C[256][12800], K=20736. BM=128 BN=128 BK=32, 8 warps (64x32 warp tiles)
// A smem [m][k] pad 36 ; B smem [k][n] pad 136
// B gather: parity planes + lane-contiguous 8-float runs (sector-efficient)
// ============================================================
#define KT_STEPS 324
#define SA_EL (128*36)
#define SB_EL (32*136)
#define STAGE_EL (SA_EL + SB_EL)

__global__ __launch_bounds__(256, 2)
void prim_mma_kernel(){
    extern __shared__ float sm[];
    __shared__ int sOffs[16];          // chunk base offsets (constant over kt)
    uint32_t smb = smem_u32(sm);
    int tid   = threadIdx.x;
    int ntile = blockIdx.x;       // 0..99
    int mtile = blockIdx.y;       // 0..1
    int split = blockIdx.z;       // 0..1
    int co0 = mtile*128;
    int n0  = ntile*128;
    int koff = split*10368;

    // --- A async-load mapping: thread -> row (co0+am), 16 consecutive k ---
    int am = tid >> 1;
    int ak = (tid & 1) * 16;
    const float* wA = g_wt + (long long)(co0 + am)*20736 + koff + ak;
    uint32_t dA = smb + (uint32_t)(am*36 + ak)*4u;

    // --- B gather mapping: k-row kk = tid>>3; instr j covers n-cols 8j..8j+7,
    //     lane l7 = tid&7 takes col 8j+l7 (8 consecutive floats per 8-lane run;
    //     runs never cross the 40-wide x-row since 40 % 8 == 0) ---
    int kk = tid >> 3;
    int l7 = tid & 7;
    if (tid < 16){
        int n = n0 + 8*tid;
        int bb = n / 1600, p = n % 1600;
        int y = p / 40, x0 = p % 40;
        sOffs[tid] = (bb*256*88 + 2*y)*44 + x0;
    }
    uint32_t dB = smb + (uint32_t)(SA_EL + kk*136 + l7)*4u;

    float acc[16][4];
    #pragma unroll
    for (int t=0;t<16;t++){
        #pragma unroll
        for (int q=0;q<4;q++) acc[t][q] = 0.f;
    }

    int warp = tid >> 5, lane = tid & 31;
    int wm = warp & 1;
    int wn = warp >> 1;
    int grp = lane >> 2, tig = lane & 3;
    __syncthreads();   // sOffs visible

    auto issue = [&](int kt){
        uint32_t so = (uint32_t)((kt & 1) * STAGE_EL) * 4u;
        const float* a = wA + kt*32;
        cpa16(dA + so,      a);
        cpa16(dA + so + 16, a + 4);
        cpa16(dA + so + 32, a + 8);
        cpa16(dA + so + 48, a + 12);
        int kB = koff + kt*32 + kk;
        int ci = kB / 81;
        int r  = kB - ci*81;
        int ky = r / 9;
        int kx = r - ky*9;
        const float* plane = g_h2 + (kx & 1)*PSTR + ci*(88*44) + ky*44 + (kx >> 1) + l7;
        uint32_t sb = dB + so;
        #pragma unroll
        for (int j=0;j<16;j++)
            cpa4(sb + (uint32_t)(8*j)*4u, plane + sOffs[j]);
    };

    issue(0);
    asm volatile("cp.async.commit_group;\n");

    for (int kt=0; kt<KT_STEPS; kt++){
        if (kt+1 < KT_STEPS){
            issue(kt+1);
            asm volatile("cp.async.commit_group;\n");
            asm volatile("cp.async.wait_group 1;\n");
        } else {
            asm volatile("cp.async.wait_group 0;\n");
        }
        __syncthreads();

        const float* sA = sm + (kt & 1)*STAGE_EL;
        const float* sB = sA + SA_EL;

        #pragma unroll
        for (int k8=0;k8<4;k8++){
            int kb = k8*8;
            uint32_t afr[4][4], bfr[4][2];
            #pragma unroll
            for (int ms=0;ms<4;ms++){
                int m = wm*64 + ms*16;
                afr[ms][0] = __float_as_uint(sA[(m+grp  )*36 + kb+tig  ]);
                afr[ms][1] = __float_as_uint(sA[(m+grp+8)*36 + kb+tig  ]);
                afr[ms][2] = __float_as_uint(sA[(m+grp  )*36 + kb+tig+4]);
                afr[ms][3] = __float_as_uint(sA[(m+grp+8)*36 + kb+tig+4]);
            }
            #pragma unroll
            for (int ns=0;ns<4;ns++){
                int nn = wn*32 + ns*8;
                bfr[ns][0] = __float_as_uint(sB[(kb+tig  )*136 + nn+grp]);
                bfr[ns][1] = __float_as_uint(sB[(kb+tig+4)*136 + nn+grp]);
            }
            #pragma unroll
            for (int ms=0;ms<4;ms++){
                #pragma unroll
                for (int ns=0;ns<4;ns++){
                    float* c = acc[ms*4+ns];
                    asm volatile(
                        "mma.sync.aligned.m16n8k8.row.col.f32.tf32.tf32.f32 "
                        "{%0,%1,%2,%3}, {%4,%5,%6,%7}, {%8,%9}, {%0,%1,%2,%3};\n"
                        : "+f"(c[0]), "+f"(c[1]), "+f"(c[2]), "+f"(c[3])
                        : "r"(afr[ms][0]), "r"(afr[ms][1]),
                          "r"(afr[ms][2]), "r"(afr[ms][3]),
                          "r"(bfr[ns][0]), "r"(bfr[ns][1]));
                }
            }
        }
        __syncthreads();
    }

    // epilogue: raw partials to g_acc[split][co][n]
    float* dst = g_acc + (size_t)split * (256*12800);
    #pragma unroll
    for (int ms=0;ms<4;ms++){
        int coA = co0 + wm*64 + ms*16 + grp;
        #pragma unroll
        for (int ns=0;ns<4;ns++){
            int nb = n0 + wn*32 + ns*8 + 2*tig;
            float* c = acc[ms*4+ns];
            #pragma unroll
            for (int e=0;e<4;e++){
                int n  = nb + (e & 1);
                int co = coA + (e >> 1)*8;
                dst[(size_t)co*12800 + n] = c[e];
            }
        }
    }
}

// ============================================================
// combine split-K partials + bias, then squash -> g_u
// ============================================================
__global__ void combine_squash_kernel(const float* __restrict__ bias){
    int vec  = blockIdx.x*8 + (threadIdx.x >> 5);   // 102400
    int lane = threadIdx.x & 31;
    int b  = vec / 12800;
    int rem = vec % 12800;
    int co = rem / 50;
    int j  = rem % 50;
    int n  = b*1600 + j*32 + lane;
    size_t ai = (size_t)co*12800 + n;
    float val = g_acc[ai] + g_acc[ai + 256*12800] + bias[co];
    float sq = val*val;
    #pragma unroll
    for (int off=16; off; off>>=1) sq += __shfl_xor_sync(0xffffffffu, sq, off);
    float scale = sq / ((1.f + sq) * sqrtf(sq));
    g_u[((size_t)(b*256 + co))*1600 + j*32 + lane] = val*scale;
}

// ============================================================
// u_hat[b][r][c] = sum_i W[r][c][0][i] * u[b][r][i]
// ============================================================
__global__ void uhat_kernel(const float* __restrict__ W){
    int idx = blockIdx.x*256 + threadIdx.x;
    if (idx >= NR*NC) return;
    int r = idx / 10;
    float wv[32];
    const float4* wp = (const float4*)(W + (long long)idx*32);
    #pragma unroll
    for (int q=0;q<8;q++){
        float4 t = wp[q];
        wv[q*4]=t.x; wv[q*4+1]=t.y; wv[q*4+2]=t.z; wv[q*4+3]=t.w;
    }
    #pragma unroll
    for (int b=0;b<8;b++){
        const float4* up = (const float4*)(g_u + ((long long)b*NR + r)*32);
        float s = 0.f;
        #pragma unroll
        for (int q=0;q<8;q++){
            float4 t = up[q];
            s += wv[q*4]*t.x + wv[q*4+1]*t.y + wv[q*4+2]*t.z + wv[q*4+3]*t.w;
        }
        g_uhat[b*NR*NC + idx] = s;
    }
}

__global__ void zero_bij(){
    int i = blockIdx.x*256 + threadIdx.x;
    if (i < NR*NC) g_bij[i] = 0.f;
}

// ============================================================
// routing
// ============================================================
__global__ void route_s_kernel(float* __restrict__ dout, int final_it){
    int c = blockIdx.x;
    int t = threadIdx.x;
    __shared__ float sred[9][256];

    float m = -1e30f;
    for (int r=t; r<NR; r+=256) m = fmaxf(m, g_bij[r*10 + c]);
    sred[0][t] = m; __syncthreads();
    for (int off=128; off; off>>=1){
        if (t < off) sred[0][t] = fmaxf(sred[0][t], sred[0][t+off]);
        __syncthreads();
    }
    m = sred[0][0];
    __syncthreads();

    float Z = 0.f, s[8] = {0,0,0,0,0,0,0,0};
    for (int r=t; r<NR; r+=256){
        float e = expf(g_bij[r*10 + c] - m);
        Z += e;
        const float* up = g_uhat + r*10 + c;
        #pragma unroll
        for (int b=0;b<8;b++) s[b] += e * up[b*128000];
    }
    sred[0][t] = Z;
    #pragma unroll
    for (int b=0;b<8;b++) sred[1+b][t] = s[b];
    __syncthreads();
    for (int off=128; off; off>>=1){
        if (t < off){
            #pragma unroll
            for (int q=0;q<9;q++) sred[q][t] += sred[q][t+off];
        }
        __syncthreads();
    }
    if (t < 8){
        float sv = sred[1+t][0] / sred[0][0];
        float sn = sv*sv;
        float v = sn*sv / ((1.f + sn) * sqrtf(sn));
        g_v[t*10 + c] = v;
        if (final_it) dout[t*10 + c] = v;
    }
}

__global__ void route_update_kernel(){
    int idx = blockIdx.x*256 + threadIdx.x;
    if (idx >= NR*NC) return;
    int c = idx % 10;
    float a = 0.f;
    #pragma unroll
    for (int b=0;b<8;b++) a += g_uhat[b*128000 + idx] * g_v[b*10 + c];
    g_bij[idx] += a;
}

// ============================================================
// decoder
// ============================================================
__global__ void dec1_kernel(const float* __restrict__ w1, const float* __restrict__ b1){
    int idx = blockIdx.x*256 + threadIdx.x;
    int b = idx >> 9, j = idx & 511;
    float acc = b1[j];
    #pragma unroll
    for (int i=0;i<10;i++) acc += g_v[b*10 + i] * w1[i*512 + j];
    g_t1[idx] = fmaxf(acc, 0.f);
}

__global__ void dec2_kernel(const float* __restrict__ w2, const float* __restrict__ b2){
    __shared__ float sR[512];
    int j = blockIdx.x*256 + threadIdx.x;
    int b = blockIdx.y;
    for (int i=threadIdx.x; i<512; i+=256) sR[i] = g_t1[b*512 + i];
    __syncthreads();
    float acc = b2[j];
    for (int k=0;k<512;k++) acc += sR[k] * w2[k*1024 + j];
    g_t2[b*1024 + j] = fmaxf(acc, 0.f);
}

__global__ void dec3_kernel(const float* __restrict__ w3, const float* __restrict__ b3,
                            float* __restrict__ out){
    __shared__ float sRt[1024*8];
    int tid = threadIdx.x;
    int n = blockIdx.x*256 + tid;
    for (int i=tid; i<8192; i+=256){ int k = i>>3, b = i&7; sRt[i] = g_t2[b*1024 + k]; }
    __syncthreads();
    float acc[8];
    #pragma unroll
    for (int b=0;b<8;b++) acc[b] = 0.f;
    for (int k=0;k<1024;k++){
        float wv = w3[(long long)k*27648 + n];
        const float4* rp = (const float4*)(sRt + k*8);
        float4 a0 = rp[0], a1 = rp[1];
        acc[0] += wv*a0.x; acc[1] += wv*a0.y; acc[2] += wv*a0.z; acc[3] += wv*a0.w;
        acc[4] += wv*a1.x; acc[5] += wv*a1.y; acc[6] += wv*a1.z; acc[7] += wv*a1.w;
    }
    float bv = b3[n];
    #pragma unroll
    for (int b=0;b<8;b++){
        float z = acc[b] + bv;
        out[80 + b*27648 + n] = 1.f / (1.f + expf(-z));
    }
}

// ============================================================
extern "C" void kernel_launch(void* const* d_in, const int* in_sizes, int n_in,
                              void* d_out, int out_size){
    (void)in_sizes; (void)n_in; (void)out_size;
    const float* x   = (const float*)d_in[0];
    const float* c1w = (const float*)d_in[1];
    const float* c1b = (const float*)d_in[2];
    const float* pw  = (const float*)d_in[3];
    const float* pb  = (const float*)d_in[4];
    const float* dW  = (const float*)d_in[5];
    const float* w1  = (const float*)d_in[6];
    const float* b1  = (const float*)d_in[7];
    const float* w2  = (const float*)d_in[8];
    const float* b2  = (const float*)d_in[9];
    const float* w3  = (const float*)d_in[10];
    const float* b3  = (const float*)d_in[11];
    float* out = (float*)d_out;

    static int smem_set = 0;
    if (!smem_set){
        cudaFuncSetAttribute(prim_mma_kernel,
                             cudaFuncAttributeMaxDynamicSharedMemorySize,
                             2*STAGE_EL*4);
        smem_set = 1;
    }

    wround_kernel<<<5184, 256>>>(pw);
    conv1_kernel<<<dim3(128,11,8), dim3(88,2)>>>(x, c1w, c1b);
    prim_mma_kernel<<<dim3(100,2,2), 256, 2*STAGE_EL*4>>>();
    combine_squash_kernel<<<12800, 256>>>(pb);
    uhat_kernel<<<500, 256>>>(dW);
    zero_bij<<<500, 256>>>();
    for (int it=0; it<3; it++){
        route_s_kernel<<<10, 256>>>(out, it==2 ? 1 : 0);
        if (it < 2) route_update_kernel<<<500, 256>>>();
    }
    dec1_kernel<<<16, 256>>>(w1, b1);
    dec2_kernel<<<dim3(4,8), 256>>>(w2, b2);
    dec3_kernel<<<108, 256>>>(w3, b3, out);
}

// round 10
// speedup vs baseline: 3.3130x; 1.0792x over previous
#include <cuda_runtime.h>
#include <math.h>
#include <stdint.h>

#define B 8
#define C1 256
#define H1 88
#define W1 88
#define C2 256
#define H2 40
#define W2 40
#define NR 12800
#define NC 10

#define PSTR (8*256*88*44)   // parity-plane stride (elements)
#define NSPLIT 4

// ---- device scratch (no allocations allowed) ----
__device__ float g_h2[2*PSTR];             // conv1 out, parity planes, tf32-rounded
__device__ float g_wt[256*20736];          // prim weights, tf32-rounded
__device__ float g_acc[NSPLIT*256*12800]; // split-K partial sums
__device__ float g_u[B*C2*H2*W2];          // squashed u
__device__ float g_uhat[B*NR*NC];
__device__ float g_bij[NR*NC];
__device__ float g_v[B*NC];
__device__ float g_t1[B*512];
__device__ float g_t2[B*1024];

__device__ __forceinline__ uint32_t f2tf32(float f){
    uint32_t r;
    asm("cvt.rna.tf32.f32 %0, %1;" : "=r"(r) : "f"(f));
    return r;
}
__device__ __forceinline__ void cpa16(uint32_t dst, const void* src){
    asm volatile("cp.async.cg.shared.global [%0], [%1], 16;\n" :: "r"(dst), "l"(src));
}
__device__ __forceinline__ void cpa4(uint32_t dst, const void* src){
    asm volatile("cp.async.ca.shared.global [%0], [%1], 4;\n" :: "r"(dst), "l"(src));
}
__device__ __forceinline__ uint32_t smem_u32(const void* p){
    uint32_t a;
    asm("{ .reg .u64 t; cvta.to.shared.u64 t, %1; cvt.u32.u64 %0, t; }" : "=r"(a) : "l"(p));
    return a;
}

// ============================================================
// tf32 pre-round of prim weights
// ============================================================
__global__ void wround_kernel(const float* __restrict__ w){
    int i = (blockIdx.x*256 + threadIdx.x)*4;
    float4 v = *(const float4*)(w + i);
    float4 o;
    o.x = __uint_as_float(f2tf32(v.x));
    o.y = __uint_as_float(f2tf32(v.y));
    o.z = __uint_as_float(f2tf32(v.z));
    o.w = __uint_as_float(f2tf32(v.w));
    *(float4*)(g_wt + i) = o;
}

// ============================================================
// conv1: x(8,3,96,96) * w(256,3,9,9) stride1 -> relu -> tf32 -> parity planes
// g_h2[x&1][b][co][y][x>>1] ; 4 c_out per thread
// ============================================================
__global__ void conv1_kernel(const float* __restrict__ x,
                             const float* __restrict__ w,
                             const float* __restrict__ bias){
    __shared__ float sW[972];          // 4 c_out x 3 ci x 81
    __shared__ float sIn[3*16*96];
    int tx = threadIdx.x, ty = threadIdx.y;
    int tid = ty*88 + tx;
    int co0 = blockIdx.x*4;
    int y0  = blockIdx.y*8;
    int b   = blockIdx.z;

    for (int i = tid; i < 972; i += 176) sW[i] = w[co0*243 + i];
    for (int i = tid; i < 4608; i += 176){
        int ci = i / 1536, rem = i % 1536;
        int row = rem / 96, col = rem % 96;
        sIn[i] = x[((b*3+ci)*96 + (y0+row))*96 + col];
    }
    __syncthreads();

    float acc[4][4];
    #pragma unroll
    for (int c=0;c<4;c++){
        float bv = bias[co0+c];
        #pragma unroll
        for (int r=0;r<4;r++) acc[c][r]=bv;
    }

    for (int ci=0; ci<3; ci++){
        for (int ky=0; ky<9; ky++){
            #pragma unroll
            for (int kx=0; kx<9; kx++){
                float wv[4];
                #pragma unroll
                for (int c=0;c<4;c++) wv[c] = sW[c*243 + ci*81 + ky*9 + kx];
                #pragma unroll
                for (int r=0;r<4;r++){
                    float iv = sIn[ci*1536 + (ty*4 + r + ky)*96 + tx + kx];
                    #pragma unroll
                    for (int c=0;c<4;c++) acc[c][r] += wv[c]*iv;
                }
            }
        }
    }
    int pl = (tx & 1)*PSTR + (tx >> 1);
    #pragma unroll
    for (int c=0;c<4;c++){
        #pragma unroll
        for (int r=0;r<4;r++){
            int y = y0 + ty*4 + r;
            g_h2[pl + ((b*C1+co0+c)*88 + y)*44] =
                __uint_as_float(f2tf32(fmaxf(acc[c][r], 0.f)));
        }
    }
}

// ============================================================
// prim conv implicit GEMM, tf32 mma, cp.async double-buffered, split-K=4
// C[256][12800], K=20736. BM=128 BN=128 BK=32, 8 warps (64x32 warp tiles)
// A smem [m][k] pad 36 ; B smem [k][n] pad 136
// B gather: parity planes + lane-contiguous 8-float runs
// ============================================================
#define KT_STEPS 162
#define SA_EL (128*36)
#define SB_EL (32*136)
#define STAGE_EL (SA_EL + SB_EL)

__global__ __launch_bounds__(256, 2)
void prim_mma_kernel(){
    extern __shared__ float sm[];
    __shared__ int sOffs[16];
    uint32_t smb = smem_u32(sm);
    int tid   = threadIdx.x;
    int ntile = blockIdx.x;       // 0..99
    int mtile = blockIdx.y;       // 0..1
    int split = blockIdx.z;       // 0..3
    int co0 = mtile*128;
    int n0  = ntile*128;
    int koff = split*(KT_STEPS*32);

    // --- A async-load mapping: thread -> row (co0+am), 16 consecutive k ---
    int am = tid >> 1;
    int ak = (tid & 1) * 16;
    const float* wA = g_wt + (long long)(co0 + am)*20736 + koff + ak;
    uint32_t dA = smb + (uint32_t)(am*36 + ak)*4u;

    // --- B gather mapping: k-row kk = tid>>3; lane l7 covers col 8j+l7 ---
    int kk = tid >> 3;
    int l7 = tid & 7;
    if (tid < 16){
        int n = n0 + 8*tid;
        int bb = n / 1600, p = n % 1600;
        int y = p / 40, x0 = p % 40;
        sOffs[tid] = (bb*256*88 + 2*y)*44 + x0;
    }
    uint32_t dB = smb + (uint32_t)(SA_EL + kk*136 + l7)*4u;

    float acc[16][4];
    #pragma unroll
    for (int t=0;t<16;t++){
        #pragma unroll
        for (int q=0;q<4;q++) acc[t][q] = 0.f;
    }

    int warp = tid >> 5, lane = tid & 31;
    int wm = warp & 1;
    int wn = warp >> 1;
    int grp = lane >> 2, tig = lane & 3;
    __syncthreads();   // sOffs visible

    auto issue = [&](int kt){
        uint32_t so = (uint32_t)((kt & 1) * STAGE_EL) * 4u;
        const float* a = wA + kt*32;
        cpa16(dA + so,      a);
        cpa16(dA + so + 16, a + 4);
        cpa16(dA + so + 32, a + 8);
        cpa16(dA + so + 48, a + 12);
        int kB = koff + kt*32 + kk;
        int ci = kB / 81;
        int r  = kB - ci*81;
        int ky = r / 9;
        int kx = r - ky*9;
        const float* plane = g_h2 + (kx & 1)*PSTR + ci*(88*44) + ky*44 + (kx >> 1) + l7;
        uint32_t sb = dB + so;
        #pragma unroll
        for (int j=0;j<16;j++)
            cpa4(sb + (uint32_t)(8*j)*4u, plane + sOffs[j]);
    };

    issue(0);
    asm volatile("cp.async.commit_group;\n");

    for (int kt=0; kt<KT_STEPS; kt++){
        if (kt+1 < KT_STEPS){
            issue(kt+1);
            asm volatile("cp.async.commit_group;\n");
            asm volatile("cp.async.wait_group 1;\n");
        } else {
            asm volatile("cp.async.wait_group 0;\n");
        }
        __syncthreads();

        const float* sA = sm + (kt & 1)*STAGE_EL;
        const float* sB = sA + SA_EL;

        #pragma unroll
        for (int k8=0;k8<4;k8++){
            int kb = k8*8;
            uint32_t afr[4][4], bfr[4][2];
            #pragma unroll
            for (int ms=0;ms<4;ms++){
                int m = wm*64 + ms*16;
                afr[ms][0] = __float_as_uint(sA[(m+grp  )*36 + kb+tig  ]);
                afr[ms][1] = __float_as_uint(sA[(m+grp+8)*36 + kb+tig  ]);
                afr[ms][2] = __float_as_uint(sA[(m+grp  )*36 + kb+tig+4]);
                afr[ms][3] = __float_as_uint(sA[(m+grp+8)*36 + kb+tig+4]);
            }
            #pragma unroll
            for (int ns=0;ns<4;ns++){
                int nn = wn*32 + ns*8;
                bfr[ns][0] = __float_as_uint(sB[(kb+tig  )*136 + nn+grp]);
                bfr[ns][1] = __float_as_uint(sB[(kb+tig+4)*136 + nn+grp]);
            }
            #pragma unroll
            for (int ms=0;ms<4;ms++){
                #pragma unroll
                for (int ns=0;ns<4;ns++){
                    float* c = acc[ms*4+ns];
                    asm volatile(
                        "mma.sync.aligned.m16n8k8.row.col.f32.tf32.tf32.f32 "
                        "{%0,%1,%2,%3}, {%4,%5,%6,%7}, {%8,%9}, {%0,%1,%2,%3};\n"
                        : "+f"(c[0]), "+f"(c[1]), "+f"(c[2]), "+f"(c[3])
                        : "r"(afr[ms][0]), "r"(afr[ms][1]),
                          "r"(afr[ms][2]), "r"(afr[ms][3]),
                          "r"(bfr[ns][0]), "r"(bfr[ns][1]));
                }
            }
        }
        __syncthreads();
    }

    // epilogue: raw partials to g_acc[split][co][n]
    float* dst = g_acc + (size_t)split * (256*12800);
    #pragma unroll
    for (int ms=0;ms<4;ms++){
        int coA = co0 + wm*64 + ms*16 + grp;
        #pragma unroll
        for (int ns=0;ns<4;ns++){
            int nb = n0 + wn*32 + ns*8 + 2*tig;
            float* c = acc[ms*4+ns];
            #pragma unroll
            for (int e=0;e<4;e++){
                int n  = nb + (e & 1);
                int co = coA + (e >> 1)*8;
                dst[(size_t)co*12800 + n] = c[e];
            }
        }
    }
}

// ============================================================
// combine split-K partials + bias, then squash -> g_u
// ============================================================
__global__ void combine_squash_kernel(const float* __restrict__ bias){
    int vec  = blockIdx.x*8 + (threadIdx.x >> 5);   // 102400
    int lane = threadIdx.x & 31;
    int b  = vec / 12800;
    int rem = vec % 12800;
    int co = rem / 50;
    int j  = rem % 50;
    int n  = b*1600 + j*32 + lane;
    size_t ai = (size_t)co*12800 + n;
    float val = bias[co];
    #pragma unroll
    for (int s=0;s<NSPLIT;s++) val += g_acc[ai + (size_t)s*(256*12800)];
    float sq = val*val;
    #pragma unroll
    for (int off=16; off; off>>=1) sq += __shfl_xor_sync(0xffffffffu, sq, off);
    float scale = sq / ((1.f + sq) * sqrtf(sq));
    g_u[((size_t)(b*256 + co))*1600 + j*32 + lane] = val*scale;
}

// ============================================================
// u_hat[b][r][c] = sum_i W[r][c][0][i] * u[b][r][i]
// ============================================================
__global__ void uhat_kernel(const float* __restrict__ W){
    int idx = blockIdx.x*256 + threadIdx.x;
    if (idx >= NR*NC) return;
    int r = idx / 10;
    float wv[32];
    const float4* wp = (const float4*)(W + (long long)idx*32);
    #pragma unroll
    for (int q=0;q<8;q++){
        float4 t = wp[q];
        wv[q*4]=t.x; wv[q*4+1]=t.y; wv[q*4+2]=t.z; wv[q*4+3]=t.w;
    }
    #pragma unroll
    for (int b=0;b<8;b++){
        const float4* up = (const float4*)(g_u + ((long long)b*NR + r)*32);
        float s = 0.f;
        #pragma unroll
        for (int q=0;q<8;q++){
            float4 t = up[q];
            s += wv[q*4]*t.x + wv[q*4+1]*t.y + wv[q*4+2]*t.z + wv[q*4+3]*t.w;
        }
        g_uhat[b*NR*NC + idx] = s;
    }
}

__global__ void zero_bij(){
    int i = blockIdx.x*256 + threadIdx.x;
    if (i < NR*NC) g_bij[i] = 0.f;
}

// ============================================================
// routing
// ============================================================
__global__ void route_s_kernel(float* __restrict__ dout, int final_it){
    int c = blockIdx.x;
    int t = threadIdx.x;
    __shared__ float sred[9][256];

    float m = -1e30f;
    for (int r=t; r<NR; r+=256) m = fmaxf(m, g_bij[r*10 + c]);
    sred[0][t] = m; __syncthreads();
    for (int off=128; off; off>>=1){
        if (t < off) sred[0][t] = fmaxf(sred[0][t], sred[0][t+off]);
        __syncthreads();
    }
    m = sred[0][0];
    __syncthreads();

    float Z = 0.f, s[8] = {0,0,0,0,0,0,0,0};
    for (int r=t; r<NR; r+=256){
        float e = expf(g_bij[r*10 + c] - m);
        Z += e;
        const float* up = g_uhat + r*10 + c;
        #pragma unroll
        for (int b=0;b<8;b++) s[b] += e * up[b*128000];
    }
    sred[0][t] = Z;
    #pragma unroll
    for (int b=0;b<8;b++) sred[1+b][t] = s[b];
    __syncthreads();
    for (int off=128; off; off>>=1){
        if (t < off){
            #pragma unroll
            for (int q=0;q<9;q++) sred[q][t] += sred[q][t+off];
        }
        __syncthreads();
    }
    if (t < 8){
        float sv = sred[1+t][0] / sred[0][0];
        float sn = sv*sv;
        float v = sn*sv / ((1.f + sn) * sqrtf(sn));
        g_v[t*10 + c] = v;
        if (final_it) dout[t*10 + c] = v;
    }
}

__global__ void route_update_kernel(){
    int idx = blockIdx.x*256 + threadIdx.x;
    if (idx >= NR*NC) return;
    int c = idx % 10;
    float a = 0.f;
    #pragma unroll
    for (int b=0;b<8;b++) a += g_uhat[b*128000 + idx] * g_v[b*10 + c];
    g_bij[idx] += a;
}

// ============================================================
// decoder
// ============================================================
__global__ void dec1_kernel(const float* __restrict__ w1, const float* __restrict__ b1){
    int idx = blockIdx.x*256 + threadIdx.x;
    int b = idx >> 9, j = idx & 511;
    float acc = b1[j];
    #pragma unroll
    for (int i=0;i<10;i++) acc += g_v[b*10 + i] * w1[i*512 + j];
    g_t1[idx] = fmaxf(acc, 0.f);
}

__global__ void dec2_kernel(const float* __restrict__ w2, const float* __restrict__ b2){
    __shared__ float sR[512];
    int j = blockIdx.x*256 + threadIdx.x;
    int b = blockIdx.y;
    for (int i=threadIdx.x; i<512; i+=256) sR[i] = g_t1[b*512 + i];
    __syncthreads();
    float acc = b2[j];
    for (int k=0;k<512;k++) acc += sR[k] * w2[k*1024 + j];
    g_t2[b*1024 + j] = fmaxf(acc, 0.f);
}

__global__ void dec3_kernel(const float* __restrict__ w3, const float* __restrict__ b3,
                            float* __restrict__ out){
    __shared__ float sRt[1024*8];
    int tid = threadIdx.x;
    int n = blockIdx.x*256 + tid;
    for (int i=tid; i<8192; i+=256){ int k = i>>3, b = i&7; sRt[i] = g_t2[b*1024 + k]; }
    __syncthreads();
    float acc[8];
    #pragma unroll
    for (int b=0;b<8;b++) acc[b] = 0.f;
    for (int k=0;k<1024;k++){
        float wv = w3[(long long)k*27648 + n];
        const float4* rp = (const float4*)(sRt + k*8);
        float4 a0 = rp[0], a1 = rp[1];
        acc[0] += wv*a0.x; acc[1] += wv*a0.y; acc[2] += wv*a0.z; acc[3] += wv*a0.w;
        acc[4] += wv*a1.x; acc[5] += wv*a1.y; acc[6] += wv*a1.z; acc[7] += wv*a1.w;
    }
    float bv = b3[n];
    #pragma unroll
    for (int b=0;b<8;b++){
        float z = acc[b] + bv;
        out[80 + b*27648 + n] = 1.f / (1.f + expf(-z));
    }
}

// ============================================================
extern "C" void kernel_launch(void* const* d_in, const int* in_sizes, int n_in,
                              void* d_out, int out_size){
    (void)in_sizes; (void)n_in; (void)out_size;
    const float* x   = (const float*)d_in[0];
    const float* c1w = (const float*)d_in[1];
    const float* c1b = (const float*)d_in[2];
    const float* pw  = (const float*)d_in[3];
    const float* pb  = (const float*)d_in[4];
    const float* dW  = (const float*)d_in[5];
    const float* w1  = (const float*)d_in[6];
    const float* b1  = (const float*)d_in[7];
    const float* w2  = (const float*)d_in[8];
    const float* b2  = (const float*)d_in[9];
    const float* w3  = (const float*)d_in[10];
    const float* b3  = (const float*)d_in[11];
    float* out = (float*)d_out;

    static int smem_set = 0;
    if (!smem_set){
        cudaFuncSetAttribute(prim_mma_kernel,
                             cudaFuncAttributeMaxDynamicSharedMemorySize,
                             2*STAGE_EL*4);
        smem_set = 1;
    }

    wround_kernel<<<5184, 256>>>(pw);
    conv1_kernel<<<dim3(64,11,8), dim3(88,2)>>>(x, c1w, c1b);
    prim_mma_kernel<<<dim3(100,2,NSPLIT), 256, 2*STAGE_EL*4>>>();
    combine_squash_kernel<<<12800, 256>>>(pb);
    uhat_kernel<<<500, 256>>>(dW);
    zero_bij<<<500, 256>>>();
    for (int it=0; it<3; it++){
        route_s_kernel<<<10, 256>>>(out, it==2 ? 1 : 0);
        if (it < 2) route_update_kernel<<<500, 256>>>();
    }
    dec1_kernel<<<16, 256>>>(w1, b1);
    dec2_kernel<<<dim3(4,8), 256>>>(w2, b2);
    dec3_kernel<<<108, 256>>>(w3, b3, out);
}

// round 13
// speedup vs baseline: 5.7823x; 1.7453x over previous
#include <cuda_runtime.h>
#include <cuda_fp16.h>
#include <math.h>
#include <stdint.h>

#define B 8
#define C1 256
#define H1 88
#define W1 88
#define C2 256
#define H2 40
#define W2 40
#define NR 12800
#define NC 10

#define PSTR (8*256*88*44)   // parity-plane stride (elements)
#define NSPLIT 4

// ---- device scratch (no allocations allowed) ----
__device__ __half g_h2[2*PSTR];            // conv1 out, parity planes, fp16
__device__ __half g_h2s[2*PSTR];           // shifted copy: g_h2s[j] = g_h2[j+1]
__device__ __half g_wt[256*20736];         // prim weights, fp16
__device__ float g_acc[NSPLIT*256*12800];  // split-K partial sums
__device__ float g_u[B*C2*H2*W2];          // squashed u
__device__ float g_uhat[B*NR*NC];
__device__ float g_bij[NR*NC];
__device__ float g_v[B*NC];
__device__ float g_t1[B*512];
__device__ float g_t2[B*1024];

__device__ __forceinline__ void cpa16(uint32_t dst, const void* src){
    asm volatile("cp.async.cg.shared.global [%0], [%1], 16;\n" :: "r"(dst), "l"(src));
}
__device__ __forceinline__ void cpa4(uint32_t dst, const void* src){
    asm volatile("cp.async.ca.shared.global [%0], [%1], 4;\n" :: "r"(dst), "l"(src));
}
__device__ __forceinline__ uint32_t smem_u32(const void* p){
    uint32_t a;
    asm("{ .reg .u64 t; cvta.to.shared.u64 t, %1; cvt.u32.u64 %0, t; }" : "=r"(a) : "l"(p));
    return a;
}

// ============================================================
// fp16 pre-round of prim weights (two launches pad the ncu skip count)
// ============================================================
__global__ void wround_kernel(const float* __restrict__ w, int off){
    int i = (blockIdx.x*256 + threadIdx.x)*4 + off;
    float4 v = *(const float4*)(w + i);
    *(__half2*)(g_wt + i)     = __floats2half2_rn(v.x, v.y);
    *(__half2*)(g_wt + i + 2) = __floats2half2_rn(v.z, v.w);
}

// ============================================================
// conv1: x(8,3,96,96) * w(256,3,9,9) stride1 -> relu -> fp16 -> parity planes
// g_h2[x&1][b][co][y][x>>1] ; also shifted copy g_h2s
// ============================================================
__global__ void conv1_kernel(const float* __restrict__ x,
                             const float* __restrict__ w,
                             const float* __restrict__ bias, int b0){
    __shared__ float sW[972];          // 4 c_out x 3 ci x 81
    __shared__ float sIn[3*16*96];
    int tx = threadIdx.x, ty = threadIdx.y;
    int tid = ty*88 + tx;
    int co0 = blockIdx.x*4;
    int y0  = blockIdx.y*8;
    int b   = blockIdx.z + b0;

    for (int i = tid; i < 972; i += 176) sW[i] = w[co0*243 + i];
    for (int i = tid; i < 4608; i += 176){
        int ci = i / 1536, rem = i % 1536;
        int row = rem / 96, col = rem % 96;
        sIn[i] = x[((b*3+ci)*96 + (y0+row))*96 + col];
    }
    __syncthreads();

    float acc[4][4];
    #pragma unroll
    for (int c=0;c<4;c++){
        float bv = bias[co0+c];
        #pragma unroll
        for (int r=0;r<4;r++) acc[c][r]=bv;
    }

    for (int ci=0; ci<3; ci++){
        for (int ky=0; ky<9; ky++){
            #pragma unroll
            for (int kx=0; kx<9; kx++){
                float wv[4];
                #pragma unroll
                for (int c=0;c<4;c++) wv[c] = sW[c*243 + ci*81 + ky*9 + kx];
                #pragma unroll
                for (int r=0;r<4;r++){
                    float iv = sIn[ci*1536 + (ty*4 + r + ky)*96 + tx + kx];
                    #pragma unroll
                    for (int c=0;c<4;c++) acc[c][r] += wv[c]*iv;
                }
            }
        }
    }
    int pl = (tx & 1)*PSTR + (tx >> 1);
    #pragma unroll
    for (int c=0;c<4;c++){
        #pragma unroll
        for (int r=0;r<4;r++){
            int y = y0 + ty*4 + r;
            int gi = pl + ((b*C1+co0+c)*88 + y)*44;
            __half hv = __float2half_rn(fmaxf(acc[c][r], 0.f));
            g_h2[gi] = hv;
            if (gi > 0) g_h2s[gi-1] = hv;
        }
    }
}

// ============================================================
// prim conv implicit GEMM, fp16 mma m16n8k16 + ldmatrix, cp.async DB, split-K=4
// C[256][12800], K=20736. BM=128 BN=128 BK=32, 8 warps (64x32 warp tiles)
// A smem [m][k] fp16 row stride 40 halfs; B smem [k][n] fp16 row stride 136 halfs
// B gather: 16 blocks of 8 n (8-half runs, 40%8==0 -> never cross x-row);
// alignment: odd (kx>>1) rows read the shifted copy g_h2s at even base
// ============================================================
#define KT_STEPS 162
#define SA_BYTES (128*40*2)     // 10240
#define SB_BYTES (32*136*2)     // 8704
#define STAGE_BYTES (SA_BYTES + SB_BYTES)

__global__ __launch_bounds__(256, 2)
void prim_mma_kernel(){
    extern __shared__ __align__(16) char sm[];
    uint32_t smb = smem_u32(sm);
    int tid   = threadIdx.x;
    int ntile = blockIdx.x;       // 0..99
    int mtile = blockIdx.y;       // 0..1
    int split = blockIdx.z;       // 0..3
    int co0 = mtile*128;
    int n0  = ntile*128;
    int koff = split*(KT_STEPS*32);

    // --- A async-load: thread -> row (co0+am), 16 consecutive k (32B) ---
    int am = tid >> 1;
    int ah = (tid & 1) * 16;
    const __half* wA = g_wt + (long long)(co0 + am)*20736 + koff + ah;
    uint32_t dA = smb + (uint32_t)(am*40 + ah)*2u;

    // --- B gather: k-row kk = tid>>3; lane l7: pair q=l7&3 of blocks j=(l7>>2)+2i ---
    int kk = tid >> 3;
    int l7 = tid & 7;
    int q2 = (l7 & 3) * 2;            // half offset of pair within 8-n block
    int myOff[8];
    #pragma unroll
    for (int i=0;i<8;i++){
        int j = (l7 >> 2) + 2*i;
        int n = n0 + 8*j;
        int bb = n / 1600, p = n % 1600;
        int y = p / 40, x0 = p % 40;
        myOff[i] = (bb*22528 + 2*y)*44 + x0 + q2;   // 22528 = 256*88
    }
    uint32_t dB = smb + (uint32_t)(SA_BYTES + kk*272 + (l7>>2)*16 + (l7&3)*4);

    float acc[16][4];
    #pragma unroll
    for (int t=0;t<16;t++){
        #pragma unroll
        for (int qq=0;qq<4;qq++) acc[t][qq] = 0.f;
    }

    int warp = tid >> 5, lane = tid & 31;
    int wm = warp & 1;
    int wn = warp >> 1;
    int grp = lane >> 2, tig = lane & 3;

    // ldmatrix per-lane address components (bytes, stage-relative)
    uint32_t aRowByte = (uint32_t)(( (wm*64 + ((lane>>3)&1)*8 + (lane&7))*40
                                    + (lane>>4)*8 )*2);
    uint32_t bRowByte = (uint32_t)(( (lane&7) + ((lane>>3)&1)*8 )*272 + (wn*32)*2);

    auto issue = [&](int kt){
        uint32_t so = (uint32_t)((kt & 1) * STAGE_BYTES);
        const __half* a = wA + kt*32;
        cpa16(dA + so,      a);
        cpa16(dA + so + 16, a + 8);
        int kB = koff + kt*32 + kk;
        int ci = kB / 81;
        int r  = kB - ci*81;
        int ky = r / 9;
        int kx = r - ky*9;
        int rowbase = ci*3872 + ky*44 + (kx >> 1);     // 3872 = 88*44
        const __half* srcb;
        if ((kx >> 1) & 1) srcb = g_h2s + (kx & 1)*PSTR + rowbase - 1;
        else               srcb = g_h2  + (kx & 1)*PSTR + rowbase;
        uint32_t sb = dB + so;
        #pragma unroll
        for (int i=0;i<8;i++)
            cpa4(sb + (uint32_t)(i*32), srcb + myOff[i]);
    };

    issue(0);
    asm volatile("cp.async.commit_group;\n");

    for (int kt=0; kt<KT_STEPS; kt++){
        if (kt+1 < KT_STEPS){
            issue(kt+1);
            asm volatile("cp.async.commit_group;\n");
            asm volatile("cp.async.wait_group 1;\n");
        } else {
            asm volatile("cp.async.wait_group 0;\n");
        }
        __syncthreads();

        uint32_t so  = (uint32_t)((kt & 1) * STAGE_BYTES);
        uint32_t sAb = smb + so + aRowByte;
        uint32_t sBb = smb + so + SA_BYTES + bRowByte;

        #pragma unroll
        for (int k16=0; k16<2; k16++){
            uint32_t afr[4][4], bfr[4][2];
            #pragma unroll
            for (int ms=0;ms<4;ms++){
                uint32_t ad = sAb + (uint32_t)(ms*1280 + k16*32);
                asm volatile(
                    "ldmatrix.sync.aligned.m8n8.x4.shared.b16 {%0,%1,%2,%3}, [%4];"
                    : "=r"(afr[ms][0]), "=r"(afr[ms][1]),
                      "=r"(afr[ms][2]), "=r"(afr[ms][3])
                    : "r"(ad));
            }
            #pragma unroll
            for (int ns=0;ns<4;ns++){
                uint32_t bd = sBb + (uint32_t)(ns*16 + k16*4352);
                asm volatile(
                    "ldmatrix.sync.aligned.m8n8.x2.trans.shared.b16 {%0,%1}, [%2];"
                    : "=r"(bfr[ns][0]), "=r"(bfr[ns][1])
                    : "r"(bd));
            }
            #pragma unroll
            for (int ms=0;ms<4;ms++){
                #pragma unroll
                for (int ns=0;ns<4;ns++){
                    float* c = acc[ms*4+ns];
                    asm volatile(
                        "mma.sync.aligned.m16n8k16.row.col.f32.f16.f16.f32 "
                        "{%0,%1,%2,%3}, {%4,%5,%6,%7}, {%8,%9}, {%0,%1,%2,%3};\n"
                        : "+f"(c[0]), "+f"(c[1]), "+f"(c[2]), "+f"(c[3])
                        : "r"(afr[ms][0]), "r"(afr[ms][1]),
                          "r"(afr[ms][2]), "r"(afr[ms][3]),
                          "r"(bfr[ns][0]), "r"(bfr[ns][1]));
                }
            }
        }
        __syncthreads();
    }

    // epilogue: raw partials to g_acc[split][co][n]
    float* dst = g_acc + (size_t)split * (256*12800);
    #pragma unroll
    for (int ms=0;ms<4;ms++){
        int coA = co0 + wm*64 + ms*16 + grp;
        #pragma unroll
        for (int ns=0;ns<4;ns++){
            int nb = n0 + wn*32 + ns*8 + 2*tig;
            float* c = acc[ms*4+ns];
            #pragma unroll
            for (int e=0;e<4;e++){
                int n  = nb + (e & 1);
                int co = coA + (e >> 1)*8;
                dst[(size_t)co*12800 + n] = c[e];
            }
        }
    }
}

// ============================================================
// combine split-K partials + bias, then squash -> g_u
// ============================================================
__global__ void combine_squash_kernel(const float* __restrict__ bias){
    int vec  = blockIdx.x*8 + (threadIdx.x >> 5);   // 102400
    int lane = threadIdx.x & 31;
    int b  = vec / 12800;
    int rem = vec % 12800;
    int co = rem / 50;
    int j  = rem % 50;
    int n  = b*1600 + j*32 + lane;
    size_t ai = (size_t)co*12800 + n;
    float val = bias[co];
    #pragma unroll
    for (int s=0;s<NSPLIT;s++) val += g_acc[ai + (size_t)s*(256*12800)];
    float sq = val*val;
    #pragma unroll
    for (int off=16; off; off>>=1) sq += __shfl_xor_sync(0xffffffffu, sq, off);
    float scale = sq / ((1.f + sq) * sqrtf(sq));
    g_u[((size_t)(b*256 + co))*1600 + j*32 + lane] = val*scale;
}

// ============================================================
// u_hat[b][r][c] = sum_i W[r][c][0][i] * u[b][r][i]
// ============================================================
__global__ void uhat_kernel(const float* __restrict__ W){
    int idx = blockIdx.x*256 + threadIdx.x;
    if (idx >= NR*NC) return;
    int r = idx / 10;
    float wv[32];
    const float4* wp = (const float4*)(W + (long long)idx*32);
    #pragma unroll
    for (int q=0;q<8;q++){
        float4 t = wp[q];
        wv[q*4]=t.x; wv[q*4+1]=t.y; wv[q*4+2]=t.z; wv[q*4+3]=t.w;
    }
    #pragma unroll
    for (int b=0;b<8;b++){
        const float4* up = (const float4*)(g_u + ((long long)b*NR + r)*32);
        float s = 0.f;
        #pragma unroll
        for (int q=0;q<8;q++){
            float4 t = up[q];
            s += wv[q*4]*t.x + wv[q*4+1]*t.y + wv[q*4+2]*t.z + wv[q*4+3]*t.w;
        }
        g_uhat[b*NR*NC + idx] = s;
    }
}

__global__ void zero_bij(){
    int i = blockIdx.x*256 + threadIdx.x;
    if (i < NR*NC) g_bij[i] = 0.f;
}

// ============================================================
// routing
// ============================================================
__global__ void route_s_kernel(float* __restrict__ dout, int final_it){
    int c = blockIdx.x;
    int t = threadIdx.x;
    __shared__ float sred[9][256];

    float m = -1e30f;
    for (int r=t; r<NR; r+=256) m = fmaxf(m, g_bij[r*10 + c]);
    sred[0][t] = m; __syncthreads();
    for (int off=128; off; off>>=1){
        if (t < off) sred[0][t] = fmaxf(sred[0][t], sred[0][t+off]);
        __syncthreads();
    }
    m = sred[0][0];
    __syncthreads();

    float Z = 0.f, s[8] = {0,0,0,0,0,0,0,0};
    for (int r=t; r<NR; r+=256){
        float e = expf(g_bij[r*10 + c] - m);
        Z += e;
        const float* up = g_uhat + r*10 + c;
        #pragma unroll
        for (int b=0;b<8;b++) s[b] += e * up[b*128000];
    }
    sred[0][t] = Z;
    #pragma unroll
    for (int b=0;b<8;b++) sred[1+b][t] = s[b];
    __syncthreads();
    for (int off=128; off; off>>=1){
        if (t < off){
            #pragma unroll
            for (int q=0;q<9;q++) sred[q][t] += sred[q][t+off];
        }
        __syncthreads();
    }
    if (t < 8){
        float sv = sred[1+t][0] / sred[0][0];
        float sn = sv*sv;
        float v = sn*sv / ((1.f + sn) * sqrtf(sn));
        g_v[t*10 + c] = v;
        if (final_it) dout[t*10 + c] = v;
    }
}

__global__ void route_update_kernel(){
    int idx = blockIdx.x*256 + threadIdx.x;
    if (idx >= NR*NC) return;
    int c = idx % 10;
    float a = 0.f;
    #pragma unroll
    for (int b=0;b<8;b++) a += g_uhat[b*128000 + idx] * g_v[b*10 + c];
    g_bij[idx] += a;
}

// ============================================================
// decoder
// ============================================================
__global__ void dec1_kernel(const float* __restrict__ w1, const float* __restrict__ b1){
    int idx = blockIdx.x*256 + threadIdx.x;
    int b = idx >> 9, j = idx & 511;
    float acc = b1[j];
    #pragma unroll
    for (int i=0;i<10;i++) acc += g_v[b*10 + i] * w1[i*512 + j];
    g_t1[idx] = fmaxf(acc, 0.f);
}

__global__ void dec2_kernel(const float* __restrict__ w2, const float* __restrict__ b2){
    __shared__ float sR[512];
    int j = blockIdx.x*256 + threadIdx.x;
    int b = blockIdx.y;
    for (int i=threadIdx.x; i<512; i+=256) sR[i] = g_t1[b*512 + i];
    __syncthreads();
    float acc = b2[j];
    for (int k=0;k<512;k++) acc += sR[k] * w2[k*1024 + j];
    g_t2[b*1024 + j] = fmaxf(acc, 0.f);
}

__global__ void dec3_kernel(const float* __restrict__ w3, const float* __restrict__ b3,
                            float* __restrict__ out){
    __shared__ float sRt[1024*8];
    int tid = threadIdx.x;
    int n = blockIdx.x*256 + tid;
    for (int i=tid; i<8192; i+=256){ int k = i>>3, b = i&7; sRt[i] = g_t2[b*1024 + k]; }
    __syncthreads();
    float acc[8];
    #pragma unroll
    for (int b=0;b<8;b++) acc[b] = 0.f;
    for (int k=0;k<1024;k++){
        float wv = w3[(long long)k*27648 + n];
        const float4* rp = (const float4*)(sRt + k*8);
        float4 a0 = rp[0], a1 = rp[1];
        acc[0] += wv*a0.x; acc[1] += wv*a0.y; acc[2] += wv*a0.z; acc[3] += wv*a0.w;
        acc[4] += wv*a1.x; acc[5] += wv*a1.y; acc[6] += wv*a1.z; acc[7] += wv*a1.w;
    }
    float bv = b3[n];
    #pragma unroll
    for (int b=0;b<8;b++){
        float z = acc[b] + bv;
        out[80 + b*27648 + n] = 1.f / (1.f + expf(-z));
    }
}

// ============================================================
extern "C" void kernel_launch(void* const* d_in, const int* in_sizes, int n_in,
                              void* d_out, int out_size){
    (void)in_sizes; (void)n_in; (void)out_size;
    const float* x   = (const float*)d_in[0];
    const float* c1w = (const float*)d_in[1];
    const float* c1b = (const float*)d_in[2];
    const float* pw  = (const float*)d_in[3];
    const float* pb  = (const float*)d_in[4];
    const float* dW  = (const float*)d_in[5];
    const float* w1  = (const float*)d_in[6];
    const float* b1  = (const float*)d_in[7];
    const float* w2  = (const float*)d_in[8];
    const float* b2  = (const float*)d_in[9];
    const float* w3  = (const float*)d_in[10];
    const float* b3  = (const float*)d_in[11];
    float* out = (float*)d_out;

    // launches 1..5 precede prim so ncu (-s 5 -c 1) profiles prim_mma_kernel
    wround_kernel<<<2592, 256>>>(pw, 0);
    wround_kernel<<<2592, 256>>>(pw, 2592*1024);
    conv1_kernel<<<dim3(64,11,4), dim3(88,2)>>>(x, c1w, c1b, 0);
    conv1_kernel<<<dim3(64,11,4), dim3(88,2)>>>(x, c1w, c1b, 4);
    zero_bij<<<500, 256>>>();
    prim_mma_kernel<<<dim3(100,2,NSPLIT), 256, 2*STAGE_BYTES>>>();
    combine_squash_kernel<<<12800, 256>>>(pb);
    uhat_kernel<<<500, 256>>>(dW);
    for (int it=0; it<3; it++){
        route_s_kernel<<<10, 256>>>(out, it==2 ? 1 : 0);
        if (it < 2) route_update_kernel<<<500, 256>>>();
    }
    dec1_kernel<<<16, 256>>>(w1, b1);
    dec2_kernel<<<dim3(4,8), 256>>>(w2, b2);
    dec3_kernel<<<108, 256>>>(w3, b3, out);
}

// round 14
// speedup vs baseline: 6.8367x; 1.1823x over previous
#include <cuda_runtime.h>
#include <cuda_fp16.h>
#include <math.h>
#include <stdint.h>

#define B 8
#define C1 256
#define C2 256
#define NR 12800
#define NC 10

#define PSTR (8*256*88*44)   // parity-plane stride (elements)
#define NSPLIT 4
#define XN 221184            // 8*3*96*96

// ---- device scratch (no allocations allowed) ----
__device__ __half g_h2[2*PSTR];            // conv1 out, parity planes, fp16
__device__ __half g_h2s[2*PSTR];           // shifted copy: g_h2s[j] = g_h2[j+1]
__device__ __half g_xh[XN+8];              // x in fp16
__device__ __half g_xhs[XN+8];             // shifted: g_xhs[j] = g_xh[j+1]
__device__ __half g_wc1[256*256];          // conv1 weights fp16, K padded 243->256
__device__ __half g_wt[256*20736];         // prim weights, fp16
__device__ float g_acc[NSPLIT*256*12800];  // split-K partial sums
__device__ float g_u[B*C2*1600];           // squashed u
__device__ float g_uhat[B*NR*NC];
__device__ float g_bij[NR*NC];
__device__ float g_v[B*NC];
__device__ float g_t1[B*512];
__device__ float g_t2[B*1024];

__device__ __forceinline__ void cpa16(uint32_t dst, const void* src){
    asm volatile("cp.async.cg.shared.global [%0], [%1], 16;\n" :: "r"(dst), "l"(src));
}
__device__ __forceinline__ void cpa4(uint32_t dst, const void* src){
    asm volatile("cp.async.ca.shared.global [%0], [%1], 4;\n" :: "r"(dst), "l"(src));
}
__device__ __forceinline__ uint32_t smem_u32(const void* p){
    uint32_t a;
    asm("{ .reg .u64 t; cvta.to.shared.u64 t, %1; cvt.u32.u64 %0, t; }" : "=r"(a) : "l"(p));
    return a;
}

// ============================================================
// prep kernels
// ============================================================
__global__ void wround_kernel(const float* __restrict__ w, int off){
    int i = (blockIdx.x*256 + threadIdx.x)*4 + off;
    float4 v = *(const float4*)(w + i);
    *(__half2*)(g_wt + i)     = __floats2half2_rn(v.x, v.y);
    *(__half2*)(g_wt + i + 2) = __floats2half2_rn(v.z, v.w);
}
__global__ void xround_kernel(const float* __restrict__ x){
    int i = (blockIdx.x*256 + threadIdx.x)*4;   // 216*1024 = XN
    float4 v = *(const float4*)(x + i);
    __half h[4];
    h[0]=__float2half_rn(v.x); h[1]=__float2half_rn(v.y);
    h[2]=__float2half_rn(v.z); h[3]=__float2half_rn(v.w);
    #pragma unroll
    for (int k=0;k<4;k++){
        g_xh[i+k] = h[k];
        if (i+k > 0) g_xhs[i+k-1] = h[k];
    }
}
__global__ void wc1round_kernel(const float* __restrict__ w){
    int idx = blockIdx.x*256 + threadIdx.x;     // 65536
    int co = idx >> 8, k = idx & 255;
    g_wc1[idx] = (k < 243) ? __float2half_rn(w[co*243 + k]) : __half(0.f);
}

// ============================================================
// shared GEMM geometry: BM=128 BN=128 BK=32, 8 warps (64x32 warp tiles)
// A smem [m][k] fp16 row stride 40 halfs; B smem [k][n] fp16 row stride 136 halfs
// ============================================================
#define SA_BYTES (128*40*2)     // 10240
#define SB_BYTES (32*136*2)     // 8704
#define STAGE_BYTES (SA_BYTES + SB_BYTES)

// ============================================================
// conv1 as implicit GEMM: C[256][61952], K=243 (padded 256)
// n = b*7744 + y*88 + xo ; Im[k][n] = x[b][ci][y+ky][xo+kx], k=ci*81+ky*9+kx
// epilogue: bias+relu -> fp16 -> parity planes g_h2/g_h2s
// ============================================================
#define C1_KT 8

__global__ __launch_bounds__(256, 2)
void conv1_mma_kernel(const float* __restrict__ bias){
    extern __shared__ __align__(16) char sm[];
    uint32_t smb = smem_u32(sm);
    int tid   = threadIdx.x;
    int ntile = blockIdx.x;       // 0..483
    int mtile = blockIdx.y;       // 0..1
    int co0 = mtile*128;
    int n0  = ntile*128;

    int am = tid >> 1;
    int ah = (tid & 1) * 16;
    const __half* wA = g_wc1 + (co0 + am)*256 + ah;
    uint32_t dA = smb + (uint32_t)(am*40 + ah)*2u;

    int kk = tid >> 3;
    int l7 = tid & 7;
    int q2 = (l7 & 3) * 2;
    int myOff[8];
    #pragma unroll
    for (int i=0;i<8;i++){
        int j = (l7 >> 2) + 2*i;
        int n = n0 + 8*j;
        int bb = n / 7744, p = n % 7744;
        int y = p / 88, xo = p % 88;
        myOff[i] = (bb*288 + y)*96 + xo + q2;    // 288 = 3*96 ; even base
    }
    uint32_t dB = smb + (uint32_t)(SA_BYTES + kk*272 + (l7>>2)*16 + (l7&3)*4);

    float acc[16][4];
    #pragma unroll
    for (int t=0;t<16;t++){
        #pragma unroll
        for (int qq=0;qq<4;qq++) acc[t][qq] = 0.f;
    }

    int warp = tid >> 5, lane = tid & 31;
    int wm = warp & 1;
    int wn = warp >> 1;
    int grp = lane >> 2, tig = lane & 3;

    uint32_t aRowByte = (uint32_t)(( (wm*64 + ((lane>>3)&1)*8 + (lane&7))*40
                                    + (lane>>4)*8 )*2);
    uint32_t bRowByte = (uint32_t)(( (lane&7) + ((lane>>3)&1)*8 )*272 + (wn*32)*2);

    auto issue = [&](int kt){
        uint32_t so = (uint32_t)((kt & 1) * STAGE_BYTES);
        const __half* a = wA + kt*32;
        cpa16(dA + so,      a);
        cpa16(dA + so + 16, a + 8);
        int k = kt*32 + kk;
        if (k >= 243) k = 0;                      // padded rows: weights are zero
        int ci = k / 81;
        int r  = k - ci*81;
        int ky = r / 9;
        int kx = r - ky*9;
        int add = ci*9216 + ky*96 + kx;           // 9216 = 96*96
        const __half* srcb = (kx & 1) ? (g_xhs + add - 1) : (g_xh + add);
        uint32_t sb = dB + so;
        #pragma unroll
        for (int i=0;i<8;i++)
            cpa4(sb + (uint32_t)(i*32), srcb + myOff[i]);
    };

    issue(0);
    asm volatile("cp.async.commit_group;\n");

    for (int kt=0; kt<C1_KT; kt++){
        if (kt+1 < C1_KT){
            issue(kt+1);
            asm volatile("cp.async.commit_group;\n");
            asm volatile("cp.async.wait_group 1;\n");
        } else {
            asm volatile("cp.async.wait_group 0;\n");
        }
        __syncthreads();

        uint32_t so  = (uint32_t)((kt & 1) * STAGE_BYTES);
        uint32_t sAb = smb + so + aRowByte;
        uint32_t sBb = smb + so + SA_BYTES + bRowByte;

        #pragma unroll
        for (int k16=0; k16<2; k16++){
            uint32_t afr[4][4], bfr[4][2];
            #pragma unroll
            for (int ms=0;ms<4;ms++){
                uint32_t ad = sAb + (uint32_t)(ms*1280 + k16*32);
                asm volatile(
                    "ldmatrix.sync.aligned.m8n8.x4.shared.b16 {%0,%1,%2,%3}, [%4];"
                    : "=r"(afr[ms][0]), "=r"(afr[ms][1]),
                      "=r"(afr[ms][2]), "=r"(afr[ms][3])
                    : "r"(ad));
            }
            #pragma unroll
            for (int ns=0;ns<4;ns++){
                uint32_t bd = sBb + (uint32_t)(ns*16 + k16*4352);
                asm volatile(
                    "ldmatrix.sync.aligned.m8n8.x2.trans.shared.b16 {%0,%1}, [%2];"
                    : "=r"(bfr[ns][0]), "=r"(bfr[ns][1])
                    : "r"(bd));
            }
            #pragma unroll
            for (int ms=0;ms<4;ms++){
                #pragma unroll
                for (int ns=0;ns<4;ns++){
                    float* c = acc[ms*4+ns];
                    asm volatile(
                        "mma.sync.aligned.m16n8k16.row.col.f32.f16.f16.f32 "
                        "{%0,%1,%2,%3}, {%4,%5,%6,%7}, {%8,%9}, {%0,%1,%2,%3};\n"
                        : "+f"(c[0]), "+f"(c[1]), "+f"(c[2]), "+f"(c[3])
                        : "r"(afr[ms][0]), "r"(afr[ms][1]),
                          "r"(afr[ms][2]), "r"(afr[ms][3]),
                          "r"(bfr[ns][0]), "r"(bfr[ns][1]));
                }
            }
        }
        __syncthreads();
    }

    // epilogue: bias + relu -> fp16 parity planes
    #pragma unroll
    for (int ms=0;ms<4;ms++){
        int coA = co0 + wm*64 + ms*16 + grp;
        float bA = bias[coA], bC = bias[coA + 8];
        #pragma unroll
        for (int ns=0;ns<4;ns++){
            int nb = n0 + wn*32 + ns*8 + 2*tig;
            float* c = acc[ms*4+ns];
            #pragma unroll
            for (int e=0;e<4;e++){
                int n  = nb + (e & 1);
                int co = coA + (e >> 1)*8;
                float val = c[e] + ((e >> 1) ? bC : bA);
                __half hv = __float2half_rn(fmaxf(val, 0.f));
                int bb = n / 7744, p = n % 7744;
                int y = p / 88, xo = p % 88;
                int gi = (xo & 1)*PSTR + (xo >> 1) + ((bb*C1 + co)*88 + y)*44;
                g_h2[gi] = hv;
                if (gi > 0) g_h2s[gi-1] = hv;
            }
        }
    }
}

// ============================================================
// prim conv implicit GEMM, fp16 mma + ldmatrix, cp.async DB, split-K=4
// ============================================================
#define KT_STEPS 162

__global__ __launch_bounds__(256, 2)
void prim_mma_kernel(){
    extern __shared__ __align__(16) char sm[];
    uint32_t smb = smem_u32(sm);
    int tid   = threadIdx.x;
    int ntile = blockIdx.x;       // 0..99
    int mtile = blockIdx.y;       // 0..1
    int split = blockIdx.z;       // 0..3
    int co0 = mtile*128;
    int n0  = ntile*128;
    int koff = split*(KT_STEPS*32);

    int am = tid >> 1;
    int ah = (tid & 1) * 16;
    const __half* wA = g_wt + (long long)(co0 + am)*20736 + koff + ah;
    uint32_t dA = smb + (uint32_t)(am*40 + ah)*2u;

    int kk = tid >> 3;
    int l7 = tid & 7;
    int q2 = (l7 & 3) * 2;
    int myOff[8];
    #pragma unroll
    for (int i=0;i<8;i++){
        int j = (l7 >> 2) + 2*i;
        int n = n0 + 8*j;
        int bb = n / 1600, p = n % 1600;
        int y = p / 40, x0 = p % 40;
        myOff[i] = (bb*22528 + 2*y)*44 + x0 + q2;   // 22528 = 256*88
    }
    uint32_t dB = smb + (uint32_t)(SA_BYTES + kk*272 + (l7>>2)*16 + (l7&3)*4);

    float acc[16][4];
    #pragma unroll
    for (int t=0;t<16;t++){
        #pragma unroll
        for (int qq=0;qq<4;qq++) acc[t][qq] = 0.f;
    }

    int warp = tid >> 5, lane = tid & 31;
    int wm = warp & 1;
    int wn = warp >> 1;
    int grp = lane >> 2, tig = lane & 3;

    uint32_t aRowByte = (uint32_t)(( (wm*64 + ((lane>>3)&1)*8 + (lane&7))*40
                                    + (lane>>4)*8 )*2);
    uint32_t bRowByte = (uint32_t)(( (lane&7) + ((lane>>3)&1)*8 )*272 + (wn*32)*2);

    auto issue = [&](int kt){
        uint32_t so = (uint32_t)((kt & 1) * STAGE_BYTES);
        const __half* a = wA + kt*32;
        cpa16(dA + so,      a);
        cpa16(dA + so + 16, a + 8);
        int kB = koff + kt*32 + kk;
        int ci = kB / 81;
        int r  = kB - ci*81;
        int ky = r / 9;
        int kx = r - ky*9;
        int rowbase = ci*3872 + ky*44 + (kx >> 1);     // 3872 = 88*44
        const __half* srcb;
        if ((kx >> 1) & 1) srcb = g_h2s + (kx & 1)*PSTR + rowbase - 1;
        else               srcb = g_h2  + (kx & 1)*PSTR + rowbase;
        uint32_t sb = dB + so;
        #pragma unroll
        for (int i=0;i<8;i++)
            cpa4(sb + (uint32_t)(i*32), srcb + myOff[i]);
    };

    issue(0);
    asm volatile("cp.async.commit_group;\n");

    for (int kt=0; kt<KT_STEPS; kt++){
        if (kt+1 < KT_STEPS){
            issue(kt+1);
            asm volatile("cp.async.commit_group;\n");
            asm volatile("cp.async.wait_group 1;\n");
        } else {
            asm volatile("cp.async.wait_group 0;\n");
        }
        __syncthreads();

        uint32_t so  = (uint32_t)((kt & 1) * STAGE_BYTES);
        uint32_t sAb = smb + so + aRowByte;
        uint32_t sBb = smb + so + SA_BYTES + bRowByte;

        #pragma unroll
        for (int k16=0; k16<2; k16++){
            uint32_t afr[4][4], bfr[4][2];
            #pragma unroll
            for (int ms=0;ms<4;ms++){
                uint32_t ad = sAb + (uint32_t)(ms*1280 + k16*32);
                asm volatile(
                    "ldmatrix.sync.aligned.m8n8.x4.shared.b16 {%0,%1,%2,%3}, [%4];"
                    : "=r"(afr[ms][0]), "=r"(afr[ms][1]),
                      "=r"(afr[ms][2]), "=r"(afr[ms][3])
                    : "r"(ad));
            }
            #pragma unroll
            for (int ns=0;ns<4;ns++){
                uint32_t bd = sBb + (uint32_t)(ns*16 + k16*4352);
                asm volatile(
                    "ldmatrix.sync.aligned.m8n8.x2.trans.shared.b16 {%0,%1}, [%2];"
                    : "=r"(bfr[ns][0]), "=r"(bfr[ns][1])
                    : "r"(bd));
            }
            #pragma unroll
            for (int ms=0;ms<4;ms++){
                #pragma unroll
                for (int ns=0;ns<4;ns++){
                    float* c = acc[ms*4+ns];
                    asm volatile(
                        "mma.sync.aligned.m16n8k16.row.col.f32.f16.f16.f32 "
                        "{%0,%1,%2,%3}, {%4,%5,%6,%7}, {%8,%9}, {%0,%1,%2,%3};\n"
                        : "+f"(c[0]), "+f"(c[1]), "+f"(c[2]), "+f"(c[3])
                        : "r"(afr[ms][0]), "r"(afr[ms][1]),
                          "r"(afr[ms][2]), "r"(afr[ms][3]),
                          "r"(bfr[ns][0]), "r"(bfr[ns][1]));
                }
            }
        }
        __syncthreads();
    }

    float* dst = g_acc + (size_t)split * (256*12800);
    #pragma unroll
    for (int ms=0;ms<4;ms++){
        int coA = co0 + wm*64 + ms*16 + grp;
        #pragma unroll
        for (int ns=0;ns<4;ns++){
            int nb = n0 + wn*32 + ns*8 + 2*tig;
            float* c = acc[ms*4+ns];
            #pragma unroll
            for (int e=0;e<4;e++){
                int n  = nb + (e & 1);
                int co = coA + (e >> 1)*8;
                dst[(size_t)co*12800 + n] = c[e];
            }
        }
    }
}

// ============================================================
// combine split-K partials + bias, then squash -> g_u
// ============================================================
__global__ void combine_squash_kernel(const float* __restrict__ bias){
    int vec  = blockIdx.x*8 + (threadIdx.x >> 5);   // 102400
    int lane = threadIdx.x & 31;
    int b  = vec / 12800;
    int rem = vec % 12800;
    int co = rem / 50;
    int j  = rem % 50;
    int n  = b*1600 + j*32 + lane;
    size_t ai = (size_t)co*12800 + n;
    float val = bias[co];
    #pragma unroll
    for (int s=0;s<NSPLIT;s++) val += g_acc[ai + (size_t)s*(256*12800)];
    float sq = val*val;
    #pragma unroll
    for (int off=16; off; off>>=1) sq += __shfl_xor_sync(0xffffffffu, sq, off);
    float scale = sq / ((1.f + sq) * sqrtf(sq));
    g_u[((size_t)(b*256 + co))*1600 + j*32 + lane] = val*scale;
}

// ============================================================
// u_hat / routing / decoder (unchanged)
// ============================================================
__global__ void uhat_kernel(const float* __restrict__ W){
    int idx = blockIdx.x*256 + threadIdx.x;
    if (idx >= NR*NC) return;
    int r = idx / 10;
    float wv[32];
    const float4* wp = (const float4*)(W + (long long)idx*32);
    #pragma unroll
    for (int q=0;q<8;q++){
        float4 t = wp[q];
        wv[q*4]=t.x; wv[q*4+1]=t.y; wv[q*4+2]=t.z; wv[q*4+3]=t.w;
    }
    #pragma unroll
    for (int b=0;b<8;b++){
        const float4* up = (const float4*)(g_u + ((long long)b*NR + r)*32);
        float s = 0.f;
        #pragma unroll
        for (int q=0;q<8;q++){
            float4 t = up[q];
            s += wv[q*4]*t.x + wv[q*4+1]*t.y + wv[q*4+2]*t.z + wv[q*4+3]*t.w;
        }
        g_uhat[b*NR*NC + idx] = s;
    }
}

__global__ void zero_bij(){
    int i = blockIdx.x*256 + threadIdx.x;
    if (i < NR*NC) g_bij[i] = 0.f;
}

__global__ void route_s_kernel(float* __restrict__ dout, int final_it){
    int c = blockIdx.x;
    int t = threadIdx.x;
    __shared__ float sred[9][256];

    float m = -1e30f;
    for (int r=t; r<NR; r+=256) m = fmaxf(m, g_bij[r*10 + c]);
    sred[0][t] = m; __syncthreads();
    for (int off=128; off; off>>=1){
        if (t < off) sred[0][t] = fmaxf(sred[0][t], sred[0][t+off]);
        __syncthreads();
    }
    m = sred[0][0];
    __syncthreads();

    float Z = 0.f, s[8] = {0,0,0,0,0,0,0,0};
    for (int r=t; r<NR; r+=256){
        float e = expf(g_bij[r*10 + c] - m);
        Z += e;
        const float* up = g_uhat + r*10 + c;
        #pragma unroll
        for (int b=0;b<8;b++) s[b] += e * up[b*128000];
    }
    sred[0][t] = Z;
    #pragma unroll
    for (int b=0;b<8;b++) sred[1+b][t] = s[b];
    __syncthreads();
    for (int off=128; off; off>>=1){
        if (t < off){
            #pragma unroll
            for (int q=0;q<9;q++) sred[q][t] += sred[q][t+off];
        }
        __syncthreads();
    }
    if (t < 8){
        float sv = sred[1+t][0] / sred[0][0];
        float sn = sv*sv;
        float v = sn*sv / ((1.f + sn) * sqrtf(sn));
        g_v[t*10 + c] = v;
        if (final_it) dout[t*10 + c] = v;
    }
}

__global__ void route_update_kernel(){
    int idx = blockIdx.x*256 + threadIdx.x;
    if (idx >= NR*NC) return;
    int c = idx % 10;
    float a = 0.f;
    #pragma unroll
    for (int b=0;b<8;b++) a += g_uhat[b*128000 + idx] * g_v[b*10 + c];
    g_bij[idx] += a;
}

__global__ void dec1_kernel(const float* __restrict__ w1, const float* __restrict__ b1){
    int idx = blockIdx.x*256 + threadIdx.x;
    int b = idx >> 9, j = idx & 511;
    float acc = b1[j];
    #pragma unroll
    for (int i=0;i<10;i++) acc += g_v[b*10 + i] * w1[i*512 + j];
    g_t1[idx] = fmaxf(acc, 0.f);
}

__global__ void dec2_kernel(const float* __restrict__ w2, const float* __restrict__ b2){
    __shared__ float sR[512];
    int j = blockIdx.x*256 + threadIdx.x;
    int b = blockIdx.y;
    for (int i=threadIdx.x; i<512; i+=256) sR[i] = g_t1[b*512 + i];
    __syncthreads();
    float acc = b2[j];
    for (int k=0;k<512;k++) acc += sR[k] * w2[k*1024 + j];
    g_t2[b*1024 + j] = fmaxf(acc, 0.f);
}

__global__ void dec3_kernel(const float* __restrict__ w3, const float* __restrict__ b3,
                            float* __restrict__ out){
    __shared__ float sRt[1024*8];
    int tid = threadIdx.x;
    int n = blockIdx.x*256 + tid;
    for (int i=tid; i<8192; i+=256){ int k = i>>3, b = i&7; sRt[i] = g_t2[b*1024 + k]; }
    __syncthreads();
    float acc[8];
    #pragma unroll
    for (int b=0;b<8;b++) acc[b] = 0.f;
    for (int k=0;k<1024;k++){
        float wv = w3[(long long)k*27648 + n];
        const float4* rp = (const float4*)(sRt + k*8);
        float4 a0 = rp[0], a1 = rp[1];
        acc[0] += wv*a0.x; acc[1] += wv*a0.y; acc[2] += wv*a0.z; acc[3] += wv*a0.w;
        acc[4] += wv*a1.x; acc[5] += wv*a1.y; acc[6] += wv*a1.z; acc[7] += wv*a1.w;
    }
    float bv = b3[n];
    #pragma unroll
    for (int b=0;b<8;b++){
        float z = acc[b] + bv;
        out[80 + b*27648 + n] = 1.f / (1.f + expf(-z));
    }
}

// ============================================================
extern "C" void kernel_launch(void* const* d_in, const int* in_sizes, int n_in,
                              void* d_out, int out_size){
    (void)in_sizes; (void)n_in; (void)out_size;
    const float* x   = (const float*)d_in[0];
    const float* c1w = (const float*)d_in[1];
    const float* c1b = (const float*)d_in[2];
    const float* pw  = (const float*)d_in[3];
    const float* pb  = (const float*)d_in[4];
    const float* dW  = (const float*)d_in[5];
    const float* w1  = (const float*)d_in[6];
    const float* b1  = (const float*)d_in[7];
    const float* w2  = (const float*)d_in[8];
    const float* b2  = (const float*)d_in[9];
    const float* w3  = (const float*)d_in[10];
    const float* b3  = (const float*)d_in[11];
    float* out = (float*)d_out;

    static int smem_set = 0;
    if (!smem_set){
        cudaFuncSetAttribute(prim_mma_kernel,
                             cudaFuncAttributeMaxDynamicSharedMemorySize, 2*STAGE_BYTES);
        cudaFuncSetAttribute(conv1_mma_kernel,
                             cudaFuncAttributeMaxDynamicSharedMemorySize, 2*STAGE_BYTES);
        smem_set = 1;
    }

    wround_kernel<<<2592, 256>>>(pw, 0);
    wround_kernel<<<2592, 256>>>(pw, 2592*1024);
    xround_kernel<<<216, 256>>>(x);
    wc1round_kernel<<<256, 256>>>(c1w);
    zero_bij<<<500, 256>>>();
    conv1_mma_kernel<<<dim3(484,2), 256, 2*STAGE_BYTES>>>(c1b);
    prim_mma_kernel<<<dim3(100,2,NSPLIT), 256, 2*STAGE_BYTES>>>();
    combine_squash_kernel<<<12800, 256>>>(pb);
    uhat_kernel<<<500, 256>>>(dW);
    for (int it=0; it<3; it++){
        route_s_kernel<<<10, 256>>>(out, it==2 ? 1 : 0);
        if (it < 2) route_update_kernel<<<500, 256>>>();
    }
    dec1_kernel<<<16, 256>>>(w1, b1);
    dec2_kernel<<<dim3(4,8), 256>>>(w2, b2);
    dec3_kernel<<<108, 256>>>(w3, b3, out);
}